// round 8
// baseline (speedup 1.0000x reference)
#include <cuda_runtime.h>
#include <cuda_bf16.h>
#include <cstdint>
#include <math.h>

typedef unsigned int u32;
typedef signed char s8;

// ---------------- problem constants ----------------
#define Bq     512
#define Hd     512
#define FEAT   128
#define T_ENC  512
#define PRED   96

#define GRIDSZ 128
#define NTHR   512            // 16 warps
#define INTHR  256
#define BM 64
#define BN 128
#define RPAD 80               // padded smem row stride (bytes), conflict-free

// ---------------- persistent device state ----------------
__device__ s8 g_h0h[2][Bq * Hd], g_h0l[2][Bq * Hd];
__device__ s8 g_h1h[2][Bq * Hd], g_h1l[2][Bq * Hd];
__device__ float g_fc_part[16][Bq];
__device__ float g_dec_in0[Bq];
__device__ unsigned int g_bar;
__device__ unsigned int g_max[8];   // fp32-bit maxabs: [0]=X, 1=eWh0,2=eWi0,3=eWi1,4=eWh1,5=dWh0,6=dWi1,7=dWh1

// quantized weights, permuted rows: P = tileN*128 + j, orig = (j/32)*512 + tileN*32 + (j%32)
__device__ s8 g_eWh0h[2048 * 512], g_eWh0l[2048 * 512];
__device__ s8 g_eWi0h[2048 * 128], g_eWi0l[2048 * 128];
__device__ s8 g_eWi1h[2048 * 512], g_eWi1l[2048 * 512];
__device__ s8 g_eWh1h[2048 * 512], g_eWh1l[2048 * 512];
__device__ s8 g_dWh0h[2048 * 512], g_dWh0l[2048 * 512];
__device__ s8 g_dWi1h[2048 * 512], g_dWi1l[2048 * 512];
__device__ s8 g_dWh1h[2048 * 512], g_dWh1l[2048 * 512];
__device__ s8 g_Xh[Bq * T_ENC * FEAT], g_Xl[Bq * T_ENC * FEAT];

// ---------------- smem layout ----------------
struct Chunk {                    // one K=64 chunk (64 bytes payload per row)
    s8 Ah[BM][RPAD];
    s8 Al[BM][RPAD];
    s8 Wh[BN][RPAD];
    s8 Wl[BN][RPAD];
};                                // 30720 B
#define CHB 30720u
struct SM {
    union {
        Chunk ch[2];              // 61440 B
        float gates[BM][BN];      // 32768 B
    };
};
#define SMEM_BYTES 61440

// ---------------- helpers ----------------
__device__ __forceinline__ u32 smem_u32(const void* p) {
    return (u32)__cvta_generic_to_shared(const_cast<void*>(p));
}
__device__ __forceinline__ void ldsm4(u32* r, u32 addr) {
    asm volatile("ldmatrix.sync.aligned.m8n8.x4.shared.b16 {%0,%1,%2,%3},[%4];"
                 : "=r"(r[0]), "=r"(r[1]), "=r"(r[2]), "=r"(r[3]) : "r"(addr));
}
__device__ __forceinline__ void mma_s8(int* c, const u32* a, const u32* b) {
    asm volatile("mma.sync.aligned.m16n8k32.row.col.s32.s8.s8.s32 "
                 "{%0,%1,%2,%3},{%4,%5,%6,%7},{%8,%9},{%0,%1,%2,%3};"
                 : "+r"(c[0]), "+r"(c[1]), "+r"(c[2]), "+r"(c[3])
                 : "r"(a[0]), "r"(a[1]), "r"(a[2]), "r"(a[3]), "r"(b[0]), "r"(b[1]));
}
#define CP16(d, s)  asm volatile("cp.async.cg.shared.global [%0], [%1], 16;" :: "r"(d), "l"(s) : "memory")
#define CPCOMMIT()  asm volatile("cp.async.commit_group;" ::: "memory")
#define CPWAIT0()   asm volatile("cp.async.wait_group 0;" ::: "memory")
#define CPWAIT1()   asm volatile("cp.async.wait_group 1;" ::: "memory")

__device__ __forceinline__ float sigmoidf_(float x) { return 1.0f / (1.0f + expf(-x)); }

__device__ __forceinline__ void q_split(float v, float S, s8* ph, s8* pl) {
    int q = __float2int_rn(v * S);
    q = q > 32512 ? 32512 : (q < -32512 ? -32512 : q);
    const int hi = (q + 128) >> 8;
    *ph = (s8)hi;
    *pl = (s8)(q - (hi << 8));
}

__device__ __forceinline__ void grid_bar(unsigned int* phase) {
    __syncthreads();
    if (threadIdx.x == 0) {
        __threadfence();
        atomicAdd(&g_bar, 1u);
        ++(*phase);
        const unsigned int target = (*phase) * (unsigned int)GRIDSZ;
        for (;;) {
            unsigned int v;
            asm volatile("ld.global.acquire.gpu.u32 %0, [%1];" : "=r"(v) : "l"(&g_bar));
            if (v >= target) break;
            __nanosleep(64);
        }
        __threadfence();
    }
    __syncthreads();
}

// ---------------- int8 split GEMM: facc += inv*(65536*hh + 256*(hl+lh)) ---------
// 16 warps as 4(m) x 4(n); warp tile m16 x n32; chunk K = 64 int8.
__device__ __forceinline__ void gemm_i8(float facc[4][4], float inv, SM& sm,
        const s8* __restrict__ Ah_, const s8* __restrict__ Al_, size_t lda,
        const s8* __restrict__ Wh_, const s8* __restrict__ Wl_, int K, int bm0)
{
    int ihh[4][4], ix[4][4];
#pragma unroll
    for (int j = 0; j < 4; ++j)
#pragma unroll
        for (int k = 0; k < 4; ++k) { ihh[j][k] = 0; ix[j][k] = 0; }

    const int tid = threadIdx.x, lane = tid & 31, wid = tid >> 5;
    const int wm = wid & 3, wn = wid >> 2;

    // cp.async mapping: W 128 rows x 4x16B -> 512 threads; A 64 rows x 4x16B -> tid<256
    const int wr = tid >> 2, wc = (tid & 3) << 4;
    const int ar = (tid & 255) >> 2, ac = (tid & 3) << 4;
    const bool doA = (tid < 256);

    const s8* gAh = Ah_ + (size_t)(bm0 + ar) * lda + ac;
    const s8* gAl = Al_ + (size_t)(bm0 + ar) * lda + ac;
    const s8* gWh = Wh_ + (size_t)wr * K + wc;
    const s8* gWl = Wl_ + (size_t)wr * K + wc;

    const u32 sA_h = smem_u32(&sm.ch[0].Ah[ar][ac]);
    const u32 sA_l = smem_u32(&sm.ch[0].Al[ar][ac]);
    const u32 sW_h = smem_u32(&sm.ch[0].Wh[wr][wc]);
    const u32 sW_l = smem_u32(&sm.ch[0].Wl[wr][wc]);

    // ldmatrix addressing (byte cols; identical fragment geometry to bf16 k16)
    const int q = lane >> 3, l7 = lane & 7;
    const int arow = ((q & 1) << 3) + l7, acol = (q >> 1) << 4;
    const int brow = ((q >> 1) << 3) + l7, bcol = (q & 1) << 4;
    const u32 aH  = smem_u32(&sm.ch[0].Ah[wm * 16 + arow][acol]);
    const u32 aL  = smem_u32(&sm.ch[0].Al[wm * 16 + arow][acol]);
    const u32 bH0 = smem_u32(&sm.ch[0].Wh[wn * 32 + brow][bcol]);
    const u32 bH1 = smem_u32(&sm.ch[0].Wh[wn * 32 + 16 + brow][bcol]);
    const u32 bL0 = smem_u32(&sm.ch[0].Wl[wn * 32 + brow][bcol]);
    const u32 bL1 = smem_u32(&sm.ch[0].Wl[wn * 32 + 16 + brow][bcol]);

    const int nc = K >> 6;     // chunks of 64 int8

    auto issue = [&](int c) {
        const u32 cofs = (u32)(c & 1) * CHB;
        const int k0 = c << 6;
        if (doA) { CP16(sA_h + cofs, gAh + k0); CP16(sA_l + cofs, gAl + k0); }
        CP16(sW_h + cofs, gWh + k0); CP16(sW_l + cofs, gWl + k0);
        CPCOMMIT();
    };

    __syncthreads();   // prior smem consumers done
    issue(0); issue(1);

    for (int c = 0; c < nc; ++c) {
        if (c + 1 < nc) { CPWAIT1(); } else { CPWAIT0(); }
        __syncthreads();
        const u32 cofs = (u32)(c & 1) * CHB;
#pragma unroll
        for (int ks = 0; ks < 2; ++ks) {
            const u32 off = cofs + ks * 32;
            u32 rah[4], ral[4];
            u32 rbh0[4], rbh1[4], rbl0[4], rbl1[4];
            ldsm4(rah, aH + off); ldsm4(ral, aL + off);
            ldsm4(rbh0, bH0 + off); ldsm4(rbh1, bH1 + off);
            ldsm4(rbl0, bL0 + off); ldsm4(rbl1, bL1 + off);

            mma_s8(ihh[0], rah, rbh0); mma_s8(ihh[1], rah, rbh0 + 2);
            mma_s8(ihh[2], rah, rbh1); mma_s8(ihh[3], rah, rbh1 + 2);

            mma_s8(ix[0], rah, rbl0); mma_s8(ix[1], rah, rbl0 + 2);
            mma_s8(ix[2], rah, rbl1); mma_s8(ix[3], rah, rbl1 + 2);

            mma_s8(ix[0], ral, rbh0); mma_s8(ix[1], ral, rbh0 + 2);
            mma_s8(ix[2], ral, rbh1); mma_s8(ix[3], ral, rbh1 + 2);
        }
        __syncthreads();
        if (c + 2 < nc) issue(c + 2);
    }

#pragma unroll
    for (int j = 0; j < 4; ++j)
#pragma unroll
        for (int k = 0; k < 4; ++k)
            facc[j][k] += inv * (65536.f * (float)ihh[j][k] + 256.f * (float)ix[j][k]);
}

// ---------------- epilogue: bias + LSTM pointwise, h stored as s8 hi/lo ---------
template <int MODE>
__device__ __forceinline__ void epilogue(float facc[4][4], SM& sm, float cR[4],
                                         const float* __restrict__ b_ih,
                                         const float* __restrict__ b_hh,
                                         s8* __restrict__ hH, s8* __restrict__ hL,
                                         int bm0, int hc0, int tileN,
                                         const float* __restrict__ rank1w,
                                         const float* __restrict__ y,
                                         const int* __restrict__ tf_mask,
                                         float* __restrict__ d_out, int t,
                                         const float* __restrict__ fcW,
                                         const float* __restrict__ fc_b) {
    const int tid = threadIdx.x;
    const int lane = tid & 31, wid = tid >> 5;
    const int wm = wid & 3, wn = wid >> 2;

    __syncthreads();   // all ldsm reads done before aliasing ld-region with gates
    {
        const int r0 = wm * 16 + (lane >> 2);
        const int c0 = wn * 32 + ((lane & 3) << 1);
#pragma unroll
        for (int j = 0; j < 4; ++j) {
            *(float2*)&sm.gates[r0][c0 + j * 8]     = make_float2(facc[j][0], facc[j][1]);
            *(float2*)&sm.gates[r0 + 8][c0 + j * 8] = make_float2(facc[j][2], facc[j][3]);
        }
    }
    __syncthreads();

    const int pc  = tid & 31;
    const int pr0 = (tid >> 5) * 4;
    const int col = hc0 + pc;

    const float bi = b_ih[col]        + b_hh[col];
    const float bf = b_ih[512 + col]  + b_hh[512 + col];
    const float bg = b_ih[1024 + col] + b_hh[1024 + col];
    const float bo = b_ih[1536 + col] + b_hh[1536 + col];

    float w1i = 0.f, w1f = 0.f, w1g = 0.f, w1o = 0.f, fcw = 0.f;
    if (MODE == 1) {
        w1i = rank1w[col];
        w1f = rank1w[512 + col];
        w1g = rank1w[1024 + col];
        w1o = rank1w[1536 + col];
    }
    if (MODE == 2) fcw = fcW[col];

    const bool tfprev = (MODE == 1 && t > 0) ? (tf_mask[t - 1] != 0) : false;

#pragma unroll
    for (int qq = 0; qq < 4; ++qq) {
        const int r = pr0 + qq;
        const int b = bm0 + r;

        float xi = sm.gates[r][pc]      + bi;
        float xf = sm.gates[r][32 + pc] + bf;
        float xg = sm.gates[r][64 + pc] + bg;
        float xo = sm.gates[r][96 + pc] + bo;

        if (MODE == 1) {
            float din;
            if (t == 0) {
                din = g_dec_in0[b];
            } else {
                float out = fc_b[0];
#pragma unroll
                for (int j = 0; j < 16; ++j) out += g_fc_part[j][b];
                if (tileN == 0 && pc == 0) d_out[b * PRED + (t - 1)] = out;
                din = tfprev ? y[b * PRED + t] : out;
            }
            xi += din * w1i;
            xf += din * w1f;
            xg += din * w1g;
            xo += din * w1o;
        }

        const float ii = sigmoidf_(xi);
        const float ff = sigmoidf_(xf);
        const float gg = tanhf(xg);
        const float oo = sigmoidf_(xo);
        const float c  = ff * cR[qq] + ii * gg;
        cR[qq] = c;
        const float h = oo * tanhf(c);

        q_split(h, 32512.0f, &hH[b * Hd + col], &hL[b * Hd + col]);

        if (MODE == 2) {
            float p = h * fcw;
#pragma unroll
            for (int off = 16; off > 0; off >>= 1)
                p += __shfl_xor_sync(0xFFFFFFFFu, p, off);
            if (pc == 0) g_fc_part[tileN][b] = p;
        }
    }
}

// ---------------- init kernels ----------------
__global__ void init0_kernel() {
    if (threadIdx.x < 8) g_max[threadIdx.x] = 0u;
}

__device__ void max_w(int idx, const float* __restrict__ src, int n, int gid, int stride) {
    float m = 0.0f;
    for (int i = gid; i < n; i += stride) m = fmaxf(m, fabsf(src[i]));
    atomicMax(&g_max[idx], __float_as_uint(m));
}

__global__ void initA_kernel(const float* __restrict__ Xd, const float* __restrict__ Xe,
                             const float* __restrict__ eWh0, const float* __restrict__ eWi0,
                             const float* __restrict__ eWi1, const float* __restrict__ eWh1,
                             const float* __restrict__ dWh0, const float* __restrict__ dWi1,
                             const float* __restrict__ dWh1) {
    const int tid = threadIdx.x;
    const int gid = blockIdx.x * blockDim.x + tid;
    const int stride = gridDim.x * blockDim.x;

    for (int i = gid; i < Bq * Hd; i += stride) {
        g_h0h[0][i] = 0; g_h0h[1][i] = 0; g_h0l[0][i] = 0; g_h0l[1][i] = 0;
        g_h1h[0][i] = 0; g_h1h[1][i] = 0; g_h1l[0][i] = 0; g_h1l[1][i] = 0;
    }
    if (gid == 0) g_bar = 0u;

    max_w(0, Xe, Bq * T_ENC * FEAT, gid, stride);
    max_w(1, eWh0, 2048 * 512, gid, stride);
    max_w(2, eWi0, 2048 * 128, gid, stride);
    max_w(3, eWi1, 2048 * 512, gid, stride);
    max_w(4, eWh1, 2048 * 512, gid, stride);
    max_w(5, dWh0, 2048 * 512, gid, stride);
    max_w(6, dWi1, 2048 * 512, gid, stride);
    max_w(7, dWh1, 2048 * 512, gid, stride);

    const int b = blockIdx.x;
    if (b < Bq) {
        float s = 0.0f;
        for (int i = tid; i < PRED * 8; i += blockDim.x) s += Xd[b * PRED * 8 + i];
        __shared__ float red[INTHR];
        red[tid] = s;
        __syncthreads();
        for (int off = INTHR / 2; off > 0; off >>= 1) {
            if (tid < off) red[tid] += red[tid + off];
            __syncthreads();
        }
        if (tid == 0) g_dec_in0[b] = red[0];
    }
}

__device__ void quant_w(s8* dh, s8* dl, const float* __restrict__ src,
                        int K, float S, int gid, int stride) {
    const int total = 2048 * K;
    for (int i = gid; i < total; i += stride) {
        const int P = i / K, k = i - P * K;
        const int tn = P >> 7, j = P & 127;
        const int orig = ((j >> 5) << 9) + (tn << 5) + (j & 31);
        q_split(src[orig * K + k], S, &dh[i], &dl[i]);
    }
}

__global__ void initB_kernel(const float* __restrict__ Xe,
                             const float* __restrict__ eWh0, const float* __restrict__ eWi0,
                             const float* __restrict__ eWi1, const float* __restrict__ eWh1,
                             const float* __restrict__ dWh0, const float* __restrict__ dWi1,
                             const float* __restrict__ dWh1) {
    const int gid = blockIdx.x * blockDim.x + threadIdx.x;
    const int stride = gridDim.x * blockDim.x;

    const float Sx = 32512.0f / fmaxf(__uint_as_float(g_max[0]), 1e-30f);
    {
        const int total = Bq * T_ENC * FEAT;
        for (int i = gid; i < total; i += stride)
            q_split(Xe[i], Sx, &g_Xh[i], &g_Xl[i]);
    }
    quant_w(g_eWh0h, g_eWh0l, eWh0, 512, 32512.0f / fmaxf(__uint_as_float(g_max[1]), 1e-30f), gid, stride);
    quant_w(g_eWi0h, g_eWi0l, eWi0, 128, 32512.0f / fmaxf(__uint_as_float(g_max[2]), 1e-30f), gid, stride);
    quant_w(g_eWi1h, g_eWi1l, eWi1, 512, 32512.0f / fmaxf(__uint_as_float(g_max[3]), 1e-30f), gid, stride);
    quant_w(g_eWh1h, g_eWh1l, eWh1, 512, 32512.0f / fmaxf(__uint_as_float(g_max[4]), 1e-30f), gid, stride);
    quant_w(g_dWh0h, g_dWh0l, dWh0, 512, 32512.0f / fmaxf(__uint_as_float(g_max[5]), 1e-30f), gid, stride);
    quant_w(g_dWi1h, g_dWi1l, dWi1, 512, 32512.0f / fmaxf(__uint_as_float(g_max[6]), 1e-30f), gid, stride);
    quant_w(g_dWh1h, g_dWh1l, dWh1, 512, 32512.0f / fmaxf(__uint_as_float(g_max[7]), 1e-30f), gid, stride);
}

// ---------------- persistent seq2seq kernel ----------------
__global__ __launch_bounds__(NTHR, 1) void seq2seq_kernel(
    const float* __restrict__ y, const int* __restrict__ tfm,
    const float* __restrict__ ebi0, const float* __restrict__ ebh0,
    const float* __restrict__ ebi1, const float* __restrict__ ebh1,
    const float* __restrict__ dWi0,
    const float* __restrict__ dbi0, const float* __restrict__ dbh0,
    const float* __restrict__ dbi1, const float* __restrict__ dbh1,
    const float* __restrict__ fcW, const float* __restrict__ fcB,
    float* __restrict__ d_out) {
    extern __shared__ char s_raw[];
    SM& sm = *reinterpret_cast<SM*>(s_raw);

    const int tileM = blockIdx.x >> 4;   // 0..7
    const int tileN = blockIdx.x & 15;   // 0..15
    const int bm0 = tileM * BM;
    const int hc0 = tileN * 32;
    const size_t woff512 = (size_t)tileN * 128 * 512;
    const size_t woff128 = (size_t)tileN * 128 * 128;

    // per-segment dequant factors: 1/(Sa*Sw) = maxA*maxW/32512^2
    const float R2 = (1.0f / 32512.0f) * (1.0f / 32512.0f);
    const float invEA0 = __uint_as_float(g_max[1]) * R2;
    const float invEA1 = __uint_as_float(g_max[0]) * __uint_as_float(g_max[2]) * R2;
    const float invEB0 = __uint_as_float(g_max[3]) * R2;
    const float invEB1 = __uint_as_float(g_max[4]) * R2;
    const float invDA  = __uint_as_float(g_max[5]) * R2;
    const float invDB0 = __uint_as_float(g_max[6]) * R2;
    const float invDB1 = __uint_as_float(g_max[7]) * R2;

    float c0r[4], c1r[4];
#pragma unroll
    for (int qq = 0; qq < 4; ++qq) { c0r[qq] = 0.0f; c1r[qq] = 0.0f; }

    unsigned int phase = 0;
    int par = 0;
    float facc[4][4];

#define ZERO_ACC() do { _Pragma("unroll") for (int _j = 0; _j < 4; ++_j) \
    _Pragma("unroll") for (int _k = 0; _k < 4; ++_k) facc[_j][_k] = 0.0f; } while (0)

    // ---------------- encoder (wavefront: layer0(t=s) + layer1(t=s-1)) ----------
    for (int s = 0; s < T_ENC; ++s) {
        const s8* hr0h = g_h0h[par]; const s8* hr0l = g_h0l[par];
        s8* hw0h = g_h0h[par ^ 1];   s8* hw0l = g_h0l[par ^ 1];
        const s8* hr1h = g_h1h[par]; const s8* hr1l = g_h1l[par];
        s8* hw1h = g_h1h[par ^ 1];   s8* hw1l = g_h1l[par ^ 1];

        // layer0(t=s): gates0 = h0(s-1) @ eWh0^T + x_s @ eWi0^T
        ZERO_ACC();
        gemm_i8(facc, invEA0, sm, hr0h, hr0l, Hd,
                g_eWh0h + woff512, g_eWh0l + woff512, 512, bm0);
        gemm_i8(facc, invEA1, sm, g_Xh + (size_t)s * FEAT, g_Xl + (size_t)s * FEAT,
                (size_t)T_ENC * FEAT, g_eWi0h + woff128, g_eWi0l + woff128, 128, bm0);
        epilogue<0>(facc, sm, c0r, ebi0, ebh0, hw0h, hw0l, bm0, hc0, tileN,
                    (const float*)0, (const float*)0, (const int*)0, (float*)0, s,
                    (const float*)0, (const float*)0);

        // layer1(t=s-1): gates1 = h0(s-1) @ eWi1^T + h1(s-2) @ eWh1^T
        if (s > 0) {
            ZERO_ACC();
            gemm_i8(facc, invEB0, sm, hr0h, hr0l, Hd,
                    g_eWi1h + woff512, g_eWi1l + woff512, 512, bm0);
            gemm_i8(facc, invEB1, sm, hr1h, hr1l, Hd,
                    g_eWh1h + woff512, g_eWh1l + woff512, 512, bm0);
            epilogue<0>(facc, sm, c1r, ebi1, ebh1, hw1h, hw1l, bm0, hc0, tileN,
                        (const float*)0, (const float*)0, (const int*)0, (float*)0, s,
                        (const float*)0, (const float*)0);
        }
        grid_bar(&phase);
        par ^= 1;
    }

    // tail stage: layer1(t=T_ENC-1) + copy final h0 across double buffer
    {
        const s8* hr0h = g_h0h[par]; const s8* hr0l = g_h0l[par];
        s8* hw0h = g_h0h[par ^ 1];   s8* hw0l = g_h0l[par ^ 1];
        const s8* hr1h = g_h1h[par]; const s8* hr1l = g_h1l[par];
        s8* hw1h = g_h1h[par ^ 1];   s8* hw1l = g_h1l[par ^ 1];

        ZERO_ACC();
        gemm_i8(facc, invEB0, sm, hr0h, hr0l, Hd,
                g_eWi1h + woff512, g_eWi1l + woff512, 512, bm0);
        gemm_i8(facc, invEB1, sm, hr1h, hr1l, Hd,
                g_eWh1h + woff512, g_eWh1l + woff512, 512, bm0);
        epilogue<0>(facc, sm, c1r, ebi1, ebh1, hw1h, hw1l, bm0, hc0, tileN,
                    (const float*)0, (const float*)0, (const int*)0, (float*)0, T_ENC,
                    (const float*)0, (const float*)0);

        for (int i = threadIdx.x; i < BM * 32; i += NTHR) {
            const int r = bm0 + (i >> 5), cc = hc0 + (i & 31);
            hw0h[r * Hd + cc] = hr0h[r * Hd + cc];
            hw0l[r * Hd + cc] = hr0l[r * Hd + cc];
        }
        grid_bar(&phase);
        par ^= 1;
    }

    // ---------------- decoder ----------------
    for (int t = 0; t < PRED; ++t) {
        const s8* hr0h = g_h0h[par]; const s8* hr0l = g_h0l[par];
        s8* hw0h = g_h0h[par ^ 1];   s8* hw0l = g_h0l[par ^ 1];
        const s8* hr1h = g_h1h[par]; const s8* hr1l = g_h1l[par];
        s8* hw1h = g_h1h[par ^ 1];   s8* hw1l = g_h1l[par ^ 1];

        // stage A: gates0 = h0 @ dWh0^T (+ din * dWi0 in epilogue)
        ZERO_ACC();
        gemm_i8(facc, invDA, sm, hr0h, hr0l, Hd,
                g_dWh0h + woff512, g_dWh0l + woff512, 512, bm0);
        epilogue<1>(facc, sm, c0r, dbi0, dbh0, hw0h, hw0l, bm0, hc0, tileN,
                    dWi0, y, tfm, d_out, t, (const float*)0, fcB);
        grid_bar(&phase);

        // stage B
        ZERO_ACC();
        gemm_i8(facc, invDB0, sm, hw0h, hw0l, Hd,
                g_dWi1h + woff512, g_dWi1l + woff512, 512, bm0);
        gemm_i8(facc, invDB1, sm, hr1h, hr1l, Hd,
                g_dWh1h + woff512, g_dWh1l + woff512, 512, bm0);
        epilogue<2>(facc, sm, c1r, dbi1, dbh1, hw1h, hw1l, bm0, hc0, tileN,
                    (const float*)0, (const float*)0, (const int*)0, (float*)0, t,
                    fcW, (const float*)0);
        grid_bar(&phase);
        par ^= 1;
    }

    // ---------------- final output (t = PRED-1) ----------------
    if (tileN == 0 && threadIdx.x < BM) {
        const int b = bm0 + threadIdx.x;
        float out = fcB[0];
#pragma unroll
        for (int j = 0; j < 16; ++j) out += g_fc_part[j][b];
        d_out[b * PRED + (PRED - 1)] = out;
    }
}

// ---------------- harness entry ----------------
extern "C" void kernel_launch(void* const* d_in, const int* in_sizes, int n_in,
                              void* d_out, int out_size) {
    const float* Xe  = (const float*)d_in[0];
    const float* Xd  = (const float*)d_in[1];
    const float* y   = (const float*)d_in[2];
    const int*   tfm = (const int*)d_in[3];
    const float* eWi0 = (const float*)d_in[4];
    const float* eWh0 = (const float*)d_in[5];
    const float* ebi0 = (const float*)d_in[6];
    const float* ebh0 = (const float*)d_in[7];
    const float* eWi1 = (const float*)d_in[8];
    const float* eWh1 = (const float*)d_in[9];
    const float* ebi1 = (const float*)d_in[10];
    const float* ebh1 = (const float*)d_in[11];
    const float* dWi0 = (const float*)d_in[12];
    const float* dWh0 = (const float*)d_in[13];
    const float* dbi0 = (const float*)d_in[14];
    const float* dbh0 = (const float*)d_in[15];
    const float* dWi1 = (const float*)d_in[16];
    const float* dWh1 = (const float*)d_in[17];
    const float* dbi1 = (const float*)d_in[18];
    const float* dbh1 = (const float*)d_in[19];
    const float* fcW  = (const float*)d_in[20];
    const float* fcB  = (const float*)d_in[21];
    float* out = (float*)d_out;

    cudaFuncSetAttribute(seq2seq_kernel,
                         cudaFuncAttributeMaxDynamicSharedMemorySize, SMEM_BYTES);

    init0_kernel<<<1, 32>>>();
    initA_kernel<<<1024, INTHR>>>(Xd, Xe, eWh0, eWi0, eWi1, eWh1, dWh0, dWi1, dWh1);
    initB_kernel<<<1024, INTHR>>>(Xe, eWh0, eWi0, eWi1, eWh1, dWh0, dWi1, dWh1);
    seq2seq_kernel<<<GRIDSZ, NTHR, SMEM_BYTES>>>(y, tfm,
                                                 ebi0, ebh0, ebi1, ebh1,
                                                 dWi0, dbi0, dbh0, dbi1, dbh1,
                                                 fcW, fcB, out);
}

// round 9
// speedup vs baseline: 1.0012x; 1.0012x over previous
#include <cuda_runtime.h>
#include <cuda_bf16.h>
#include <cstdint>
#include <math.h>

typedef unsigned int u32;

// ---------------- problem constants ----------------
#define Bq     512
#define Hd     512
#define FEAT   128
#define T_ENC  512
#define PRED   96

#define GRIDSZ 128
#define NTHR   512            // 16 warps: 4(m) x 4(n), warp tile m16 x n32
#define INTHR  256
#define BM 64
#define GST 132               // gates smem row stride (floats)

// ---------------- persistent device state ----------------
__device__ __nv_bfloat16 g_h0h[2][Bq * Hd], g_h0l[2][Bq * Hd];
__device__ __nv_bfloat16 g_h1h[2][Bq * Hd], g_h1l[2][Bq * Hd];
__device__ float g_fc_part[16][Bq];
__device__ float g_dec_in0[Bq];
__device__ unsigned int g_bar;

// fragment-order prepacked weights (u32 = 2 packed bf16).
// idx = ((band*nchunk + chunk)*2 + part)*256 + lane*8 + reg
// band = tileN*4 + wn (64); reg = f*2 + p; n = wn*32+f*8+(lane>>2) (orig row
// = wn*512 + tileN*32 + f*8 + (lane>>2)); k = chunk*16 + (lane&3)*2 + p*8.
__device__ u32 g_pEWh0[64 * 32 * 512];
__device__ u32 g_pEWi0[64 * 8 * 512];
__device__ u32 g_pEWi1[64 * 32 * 512];
__device__ u32 g_pEWh1[64 * 32 * 512];
__device__ u32 g_pDWh0[64 * 32 * 512];
__device__ u32 g_pDWi1[64 * 32 * 512];
__device__ u32 g_pDWh1[64 * 32 * 512];
// split encoder input, original [b][t][f] layout
__device__ __nv_bfloat16 g_Xh[Bq * T_ENC * FEAT], g_Xl[Bq * T_ENC * FEAT];

// ---------------- helpers ----------------
__device__ __forceinline__ void mma16816(float* c, const u32* a, const u32* b) {
    asm volatile("mma.sync.aligned.m16n8k16.row.col.f32.bf16.bf16.f32 "
                 "{%0,%1,%2,%3},{%4,%5,%6,%7},{%8,%9},{%0,%1,%2,%3};"
                 : "+f"(c[0]), "+f"(c[1]), "+f"(c[2]), "+f"(c[3])
                 : "r"(a[0]), "r"(a[1]), "r"(a[2]), "r"(a[3]), "r"(b[0]), "r"(b[1]));
}
__device__ __forceinline__ float sigmoidf_(float x) { return 1.0f / (1.0f + expf(-x)); }

__device__ __forceinline__ void grid_bar(unsigned int* phase) {
    __syncthreads();
    if (threadIdx.x == 0) {
        __threadfence();
        atomicAdd(&g_bar, 1u);
        ++(*phase);
        const unsigned int target = (*phase) * (unsigned int)GRIDSZ;
        for (;;) {
            unsigned int v;
            asm volatile("ld.global.acquire.gpu.u32 %0, [%1];" : "=r"(v) : "l"(&g_bar));
            if (v >= target) break;
            __nanosleep(64);
        }
        __threadfence();
    }
    __syncthreads();
}

// ---------------- sync-free register-fragment GEMM (bf16 hi/lo, 3-pass) --------
// acc[f][4]: 4 n8-fragments of warp tile m16 x n32. No smem, no __syncthreads.
__device__ __forceinline__ void gemm_frag(float acc[4][4],
        const __nv_bfloat16* __restrict__ Ah, const __nv_bfloat16* __restrict__ Al,
        size_t lda, const u32* __restrict__ pW, int nc, int bm0, int wm)
{
    const int lane = threadIdx.x & 31;
    const int g = lane >> 2;
    const int tk = (lane & 3) << 1;

    const __nv_bfloat16* pa_h  = Ah + (size_t)(bm0 + wm * 16 + g) * lda + tk;
    const __nv_bfloat16* pa_h8 = pa_h + 8 * lda;
    const __nv_bfloat16* pa_l  = Al + (size_t)(bm0 + wm * 16 + g) * lda + tk;
    const __nv_bfloat16* pa_l8 = pa_l + 8 * lda;
    const u32* pb = pW + lane * 8;

    u32 ah[4], al[4];
    uint4 bh0, bh1, bl0, bl1;

    // prologue: chunk 0
    ah[0] = *(const u32*)(pa_h);
    ah[1] = *(const u32*)(pa_h8);
    ah[2] = *(const u32*)(pa_h + 8);
    ah[3] = *(const u32*)(pa_h8 + 8);
    al[0] = *(const u32*)(pa_l);
    al[1] = *(const u32*)(pa_l8);
    al[2] = *(const u32*)(pa_l + 8);
    al[3] = *(const u32*)(pa_l8 + 8);
    bh0 = *(const uint4*)(pb);
    bh1 = *(const uint4*)(pb + 4);
    bl0 = *(const uint4*)(pb + 256);
    bl1 = *(const uint4*)(pb + 260);

    for (int c = 0; c < nc; ++c) {
        u32 nah[4], nal[4];
        uint4 nbh0, nbh1, nbl0, nbl1;
        if (c + 1 < nc) {
            const int k0 = (c + 1) << 4;
            const u32* nb = pb + (size_t)(c + 1) * 512;
            nah[0] = *(const u32*)(pa_h + k0);
            nah[1] = *(const u32*)(pa_h8 + k0);
            nah[2] = *(const u32*)(pa_h + k0 + 8);
            nah[3] = *(const u32*)(pa_h8 + k0 + 8);
            nal[0] = *(const u32*)(pa_l + k0);
            nal[1] = *(const u32*)(pa_l8 + k0);
            nal[2] = *(const u32*)(pa_l + k0 + 8);
            nal[3] = *(const u32*)(pa_l8 + k0 + 8);
            nbh0 = *(const uint4*)(nb);
            nbh1 = *(const uint4*)(nb + 4);
            nbl0 = *(const uint4*)(nb + 256);
            nbl1 = *(const uint4*)(nb + 260);
        }

        const u32 bhr[8] = {bh0.x, bh0.y, bh0.z, bh0.w, bh1.x, bh1.y, bh1.z, bh1.w};
        const u32 blr[8] = {bl0.x, bl0.y, bl0.z, bl0.w, bl1.x, bl1.y, bl1.z, bl1.w};
#pragma unroll
        for (int f = 0; f < 4; ++f) {
            mma16816(acc[f], ah, &bhr[f * 2]);
            mma16816(acc[f], ah, &blr[f * 2]);
            mma16816(acc[f], al, &bhr[f * 2]);
        }

        if (c + 1 < nc) {
#pragma unroll
            for (int i = 0; i < 4; ++i) { ah[i] = nah[i]; al[i] = nal[i]; }
            bh0 = nbh0; bh1 = nbh1; bl0 = nbl0; bl1 = nbl1;
        }
    }
}

// ---------------- epilogue: bias + LSTM pointwise ------------------------------
template <int MODE>
__device__ __forceinline__ void epilogue(float acc[4][4], float (*gates)[GST],
                                         float cR[4],
                                         const float* __restrict__ b_ih,
                                         const float* __restrict__ b_hh,
                                         __nv_bfloat16* __restrict__ hH,
                                         __nv_bfloat16* __restrict__ hL,
                                         int bm0, int hc0, int tileN,
                                         const float* __restrict__ rank1w,
                                         const float* __restrict__ y,
                                         const int* __restrict__ tf_mask,
                                         float* __restrict__ d_out, int t,
                                         const float* __restrict__ fcW,
                                         const float* __restrict__ fc_b) {
    const int tid = threadIdx.x;
    const int lane = tid & 31, wid = tid >> 5;
    const int wm = wid & 3, wn = wid >> 2;

    __syncthreads();   // all warps done reading previous gates contents
    {
        const int r0 = wm * 16 + (lane >> 2);
        const int c0 = wn * 32 + ((lane & 3) << 1);
#pragma unroll
        for (int j = 0; j < 4; ++j) {
            *(float2*)&gates[r0][c0 + j * 8]     = make_float2(acc[j][0], acc[j][1]);
            *(float2*)&gates[r0 + 8][c0 + j * 8] = make_float2(acc[j][2], acc[j][3]);
        }
    }
    __syncthreads();

    const int pc  = tid & 31;
    const int pr0 = (tid >> 5) * 4;
    const int col = hc0 + pc;

    const float bi = b_ih[col]        + b_hh[col];
    const float bf = b_ih[512 + col]  + b_hh[512 + col];
    const float bg = b_ih[1024 + col] + b_hh[1024 + col];
    const float bo = b_ih[1536 + col] + b_hh[1536 + col];

    float w1i = 0.f, w1f = 0.f, w1g = 0.f, w1o = 0.f, fcw = 0.f;
    if (MODE == 1) {
        w1i = rank1w[col];
        w1f = rank1w[512 + col];
        w1g = rank1w[1024 + col];
        w1o = rank1w[1536 + col];
    }
    if (MODE == 2) fcw = fcW[col];

    const bool tfprev = (MODE == 1 && t > 0) ? (tf_mask[t - 1] != 0) : false;

#pragma unroll
    for (int qq = 0; qq < 4; ++qq) {
        const int r = pr0 + qq;
        const int b = bm0 + r;

        float xi = gates[r][pc]      + bi;
        float xf = gates[r][32 + pc] + bf;
        float xg = gates[r][64 + pc] + bg;
        float xo = gates[r][96 + pc] + bo;

        if (MODE == 1) {
            float din;
            if (t == 0) {
                din = g_dec_in0[b];
            } else {
                float out = fc_b[0];
#pragma unroll
                for (int j = 0; j < 16; ++j) out += g_fc_part[j][b];
                if (tileN == 0 && pc == 0) d_out[b * PRED + (t - 1)] = out;
                din = tfprev ? y[b * PRED + t] : out;
            }
            xi += din * w1i;
            xf += din * w1f;
            xg += din * w1g;
            xo += din * w1o;
        }

        const float ii = sigmoidf_(xi);
        const float ff = sigmoidf_(xf);
        const float gg = tanhf(xg);
        const float oo = sigmoidf_(xo);
        const float c  = ff * cR[qq] + ii * gg;
        cR[qq] = c;
        const float h = oo * tanhf(c);

        __nv_bfloat16 hh = __float2bfloat16(h);
        hH[b * Hd + col] = hh;
        hL[b * Hd + col] = __float2bfloat16(h - __bfloat162float(hh));

        if (MODE == 2) {
            float p = h * fcw;
#pragma unroll
            for (int off = 16; off > 0; off >>= 1)
                p += __shfl_xor_sync(0xFFFFFFFFu, p, off);
            if (pc == 0) g_fc_part[tileN][b] = p;
        }
    }
}

// ---------------- init: prepack weights, split X, zero h, seed -----------------
__device__ __forceinline__ u32 pack_bf2(__nv_bfloat16 a, __nv_bfloat16 b) {
    return (u32)__bfloat16_as_ushort(a) | ((u32)__bfloat16_as_ushort(b) << 16);
}

__device__ void prepack(u32* dst, const float* __restrict__ src,
                        int K, int lgnc, int gid, int stride) {
    const int nc = 1 << lgnc;
    const int total = 64 * nc * 512;
    for (int i = gid; i < total; i += stride) {
        const int reg = i & 7, lane = (i >> 3) & 31, part = (i >> 8) & 1;
        const int tt = i >> 9;
        const int chunk = tt & (nc - 1), band = tt >> lgnc;
        const int tileN = band >> 2, wn = band & 3;
        const int f = reg >> 1, p = reg & 1;
        const int orig = wn * 512 + tileN * 32 + f * 8 + (lane >> 2);
        const int k = chunk * 16 + ((lane & 3) << 1) + p * 8;
        const float v0 = src[(size_t)orig * K + k];
        const float v1 = src[(size_t)orig * K + k + 1];
        const __nv_bfloat16 h0 = __float2bfloat16(v0);
        const __nv_bfloat16 h1 = __float2bfloat16(v1);
        if (part == 0) {
            dst[i] = pack_bf2(h0, h1);
        } else {
            dst[i] = pack_bf2(__float2bfloat16(v0 - __bfloat162float(h0)),
                              __float2bfloat16(v1 - __bfloat162float(h1)));
        }
    }
}

__global__ void init_kernel(const float* __restrict__ Xd, const float* __restrict__ Xe,
                            const float* __restrict__ eWi0, const float* __restrict__ eWh0,
                            const float* __restrict__ eWi1, const float* __restrict__ eWh1,
                            const float* __restrict__ dWh0, const float* __restrict__ dWi1,
                            const float* __restrict__ dWh1) {
    const int tid = threadIdx.x;
    const int gid = blockIdx.x * blockDim.x + tid;
    const int stride = gridDim.x * blockDim.x;

    const __nv_bfloat16 z = __float2bfloat16(0.f);
    for (int i = gid; i < Bq * Hd; i += stride) {
        g_h0h[0][i] = z; g_h0h[1][i] = z;
        g_h0l[0][i] = z; g_h0l[1][i] = z;
        g_h1h[0][i] = z; g_h1h[1][i] = z;
        g_h1l[0][i] = z; g_h1l[1][i] = z;
    }
    if (gid == 0) g_bar = 0u;

    {
        const int total = Bq * T_ENC * FEAT;
        for (int i = gid; i < total; i += stride) {
            const float v = Xe[i];
            const __nv_bfloat16 hh = __float2bfloat16(v);
            g_Xh[i] = hh;
            g_Xl[i] = __float2bfloat16(v - __bfloat162float(hh));
        }
    }

    prepack(g_pEWh0, eWh0, 512, 5, gid, stride);
    prepack(g_pEWi0, eWi0, 128, 3, gid, stride);
    prepack(g_pEWi1, eWi1, 512, 5, gid, stride);
    prepack(g_pEWh1, eWh1, 512, 5, gid, stride);
    prepack(g_pDWh0, dWh0, 512, 5, gid, stride);
    prepack(g_pDWi1, dWi1, 512, 5, gid, stride);
    prepack(g_pDWh1, dWh1, 512, 5, gid, stride);

    const int b = blockIdx.x;
    if (b < Bq) {
        float s = 0.0f;
        for (int i = tid; i < PRED * 8; i += blockDim.x) s += Xd[b * PRED * 8 + i];
        __shared__ float red[INTHR];
        red[tid] = s;
        __syncthreads();
        for (int off = INTHR / 2; off > 0; off >>= 1) {
            if (tid < off) red[tid] += red[tid + off];
            __syncthreads();
        }
        if (tid == 0) g_dec_in0[b] = red[0];
    }
}

// ---------------- persistent seq2seq kernel ----------------
__global__ __launch_bounds__(NTHR, 1) void seq2seq_kernel(
    const float* __restrict__ y, const int* __restrict__ tfm,
    const float* __restrict__ ebi0, const float* __restrict__ ebh0,
    const float* __restrict__ ebi1, const float* __restrict__ ebh1,
    const float* __restrict__ dWi0,
    const float* __restrict__ dbi0, const float* __restrict__ dbh0,
    const float* __restrict__ dbi1, const float* __restrict__ dbh1,
    const float* __restrict__ fcW, const float* __restrict__ fcB,
    float* __restrict__ d_out) {
    __shared__ float gates[BM][GST];

    const int tid = threadIdx.x, wid = tid >> 5;
    const int wm = wid & 3, wn = wid >> 2;

    const int tileM = blockIdx.x >> 4;   // 0..7
    const int tileN = blockIdx.x & 15;   // 0..15
    const int bm0 = tileM * BM;
    const int hc0 = tileN * 32;

    const int band = tileN * 4 + wn;
    const u32* pEWh0 = g_pEWh0 + (size_t)band * 32 * 512;
    const u32* pEWi0 = g_pEWi0 + (size_t)band * 8 * 512;
    const u32* pEWi1 = g_pEWi1 + (size_t)band * 32 * 512;
    const u32* pEWh1 = g_pEWh1 + (size_t)band * 32 * 512;
    const u32* pDWh0 = g_pDWh0 + (size_t)band * 32 * 512;
    const u32* pDWi1 = g_pDWi1 + (size_t)band * 32 * 512;
    const u32* pDWh1 = g_pDWh1 + (size_t)band * 32 * 512;

    float c0r[4], c1r[4];
#pragma unroll
    for (int qq = 0; qq < 4; ++qq) { c0r[qq] = 0.0f; c1r[qq] = 0.0f; }

    unsigned int phase = 0;
    int par = 0;
    float acc[4][4];

#define ZERO_ACC() do { _Pragma("unroll") for (int _j = 0; _j < 4; ++_j) \
    _Pragma("unroll") for (int _k = 0; _k < 4; ++_k) acc[_j][_k] = 0.0f; } while (0)

    // ---------------- encoder (wavefront: layer0(t=s) + layer1(t=s-1)) ----------
    for (int s = 0; s < T_ENC; ++s) {
        const __nv_bfloat16* hr0h = g_h0h[par];
        const __nv_bfloat16* hr0l = g_h0l[par];
        __nv_bfloat16* hw0h = g_h0h[par ^ 1];
        __nv_bfloat16* hw0l = g_h0l[par ^ 1];
        const __nv_bfloat16* hr1h = g_h1h[par];
        const __nv_bfloat16* hr1l = g_h1l[par];
        __nv_bfloat16* hw1h = g_h1h[par ^ 1];
        __nv_bfloat16* hw1l = g_h1l[par ^ 1];

        // layer0(t=s)
        ZERO_ACC();
        gemm_frag(acc, hr0h, hr0l, Hd, pEWh0, 32, bm0, wm);
        gemm_frag(acc, g_Xh + (size_t)s * FEAT, g_Xl + (size_t)s * FEAT,
                  (size_t)T_ENC * FEAT, pEWi0, 8, bm0, wm);
        epilogue<0>(acc, gates, c0r, ebi0, ebh0, hw0h, hw0l, bm0, hc0, tileN,
                    (const float*)0, (const float*)0, (const int*)0, (float*)0, s,
                    (const float*)0, (const float*)0);

        // layer1(t=s-1)
        if (s > 0) {
            ZERO_ACC();
            gemm_frag(acc, hr0h, hr0l, Hd, pEWi1, 32, bm0, wm);
            gemm_frag(acc, hr1h, hr1l, Hd, pEWh1, 32, bm0, wm);
            epilogue<0>(acc, gates, c1r, ebi1, ebh1, hw1h, hw1l, bm0, hc0, tileN,
                        (const float*)0, (const float*)0, (const int*)0, (float*)0, s,
                        (const float*)0, (const float*)0);
        }
        grid_bar(&phase);
        par ^= 1;
    }

    // tail stage: layer1(t=T_ENC-1) + copy final h0 across double buffer
    {
        const __nv_bfloat16* hr0h = g_h0h[par];
        const __nv_bfloat16* hr0l = g_h0l[par];
        __nv_bfloat16* hw0h = g_h0h[par ^ 1];
        __nv_bfloat16* hw0l = g_h0l[par ^ 1];
        const __nv_bfloat16* hr1h = g_h1h[par];
        const __nv_bfloat16* hr1l = g_h1l[par];
        __nv_bfloat16* hw1h = g_h1h[par ^ 1];
        __nv_bfloat16* hw1l = g_h1l[par ^ 1];

        ZERO_ACC();
        gemm_frag(acc, hr0h, hr0l, Hd, pEWi1, 32, bm0, wm);
        gemm_frag(acc, hr1h, hr1l, Hd, pEWh1, 32, bm0, wm);
        epilogue<0>(acc, gates, c1r, ebi1, ebh1, hw1h, hw1l, bm0, hc0, tileN,
                    (const float*)0, (const float*)0, (const int*)0, (float*)0, T_ENC,
                    (const float*)0, (const float*)0);

        for (int i = tid; i < BM * 32; i += NTHR) {
            const int r = bm0 + (i >> 5), cc = hc0 + (i & 31);
            hw0h[r * Hd + cc] = hr0h[r * Hd + cc];
            hw0l[r * Hd + cc] = hr0l[r * Hd + cc];
        }
        grid_bar(&phase);
        par ^= 1;
    }

    // ---------------- decoder ----------------
    for (int t = 0; t < PRED; ++t) {
        const __nv_bfloat16* hr0h = g_h0h[par];
        const __nv_bfloat16* hr0l = g_h0l[par];
        __nv_bfloat16* hw0h = g_h0h[par ^ 1];
        __nv_bfloat16* hw0l = g_h0l[par ^ 1];
        const __nv_bfloat16* hr1h = g_h1h[par];
        const __nv_bfloat16* hr1l = g_h1l[par];
        __nv_bfloat16* hw1h = g_h1h[par ^ 1];
        __nv_bfloat16* hw1l = g_h1l[par ^ 1];

        // stage A: gates0 = h0 @ dWh0^T (+ din * dWi0 in epilogue)
        ZERO_ACC();
        gemm_frag(acc, hr0h, hr0l, Hd, pDWh0, 32, bm0, wm);
        epilogue<1>(acc, gates, c0r, dbi0, dbh0, hw0h, hw0l, bm0, hc0, tileN,
                    dWi0, y, tfm, d_out, t, (const float*)0, fcB);
        grid_bar(&phase);

        // stage B
        ZERO_ACC();
        gemm_frag(acc, hw0h, hw0l, Hd, pDWi1, 32, bm0, wm);
        gemm_frag(acc, hr1h, hr1l, Hd, pDWh1, 32, bm0, wm);
        epilogue<2>(acc, gates, c1r, dbi1, dbh1, hw1h, hw1l, bm0, hc0, tileN,
                    (const float*)0, (const float*)0, (const int*)0, (float*)0, t,
                    fcW, (const float*)0);
        grid_bar(&phase);
        par ^= 1;
    }

    // ---------------- final output (t = PRED-1) ----------------
    if (tileN == 0 && tid < BM) {
        const int b = bm0 + tid;
        float out = fcB[0];
#pragma unroll
        for (int j = 0; j < 16; ++j) out += g_fc_part[j][b];
        d_out[b * PRED + (PRED - 1)] = out;
    }
}

// ---------------- harness entry ----------------
extern "C" void kernel_launch(void* const* d_in, const int* in_sizes, int n_in,
                              void* d_out, int out_size) {
    const float* Xe  = (const float*)d_in[0];
    const float* Xd  = (const float*)d_in[1];
    const float* y   = (const float*)d_in[2];
    const int*   tfm = (const int*)d_in[3];
    const float* eWi0 = (const float*)d_in[4];
    const float* eWh0 = (const float*)d_in[5];
    const float* ebi0 = (const float*)d_in[6];
    const float* ebh0 = (const float*)d_in[7];
    const float* eWi1 = (const float*)d_in[8];
    const float* eWh1 = (const float*)d_in[9];
    const float* ebi1 = (const float*)d_in[10];
    const float* ebh1 = (const float*)d_in[11];
    const float* dWi0 = (const float*)d_in[12];
    const float* dWh0 = (const float*)d_in[13];
    const float* dbi0 = (const float*)d_in[14];
    const float* dbh0 = (const float*)d_in[15];
    const float* dWi1 = (const float*)d_in[16];
    const float* dWh1 = (const float*)d_in[17];
    const float* dbi1 = (const float*)d_in[18];
    const float* dbh1 = (const float*)d_in[19];
    const float* fcW  = (const float*)d_in[20];
    const float* fcB  = (const float*)d_in[21];
    float* out = (float*)d_out;

    init_kernel<<<1024, INTHR>>>(Xd, Xe, eWi0, eWh0, eWi1, eWh1, dWh0, dWi1, dWh1);
    seq2seq_kernel<<<GRIDSZ, NTHR>>>(y, tfm,
                                     ebi0, ebh0, ebi1, ebh1,
                                     dWi0, dbi0, dbh0, dbi1, dbh1,
                                     fcW, fcB, out);
}

// round 10
// speedup vs baseline: 2.0173x; 2.0148x over previous
#include <cuda_runtime.h>
#include <cuda_bf16.h>
#include <cstdint>
#include <math.h>

typedef unsigned int u32;

// ---------------- problem constants ----------------
#define Bq     512
#define Hd     512
#define FEAT   128
#define T_ENC  512
#define PRED   96

#define GRIDSZ 128
#define NTHR   256            // 8 warps: 2(m) x 4(n), warp tile m32 x n32
#define INTHR  256
#define BM 64
#define BN 128

// ---------------- smem layout (manual, dynamic) ----------------
// chunk (K=64): Ah[64][144B] Al[64][144B] Wh[128][144B] Wl[128][144B]
#define RPB   144u            // row pitch bytes (128B payload + 16B pad)
#define A_SZ  9216u           // 64*144
#define W_SZ  18432u          // 128*144
#define CHB   55296u          // 2*A_SZ + 2*W_SZ
#define NBUF  4
#define SMEM_BYTES (NBUF * CHB)   // 221184

// ---------------- persistent device state ----------------
__device__ __nv_bfloat16 g_h0h[2][Bq * Hd], g_h0l[2][Bq * Hd];
__device__ __nv_bfloat16 g_h1h[2][Bq * Hd], g_h1l[2][Bq * Hd];
__device__ float g_fc_part[16][Bq];
__device__ float g_dec_in0[Bq];
__device__ unsigned int g_bar;

// split weights, permuted rows: P = tileN*128 + j, orig = (j/32)*512 + tileN*32 + (j%32)
__device__ __nv_bfloat16 g_eWh0h[2048 * 512], g_eWh0l[2048 * 512];
__device__ __nv_bfloat16 g_eWi0h[2048 * 128], g_eWi0l[2048 * 128];
__device__ __nv_bfloat16 g_eWi1h[2048 * 512], g_eWi1l[2048 * 512];
__device__ __nv_bfloat16 g_eWh1h[2048 * 512], g_eWh1l[2048 * 512];
__device__ __nv_bfloat16 g_dWh0h[2048 * 512], g_dWh0l[2048 * 512];
__device__ __nv_bfloat16 g_dWi1h[2048 * 512], g_dWi1l[2048 * 512];
__device__ __nv_bfloat16 g_dWh1h[2048 * 512], g_dWh1l[2048 * 512];
__device__ __nv_bfloat16 g_Xh[Bq * T_ENC * FEAT], g_Xl[Bq * T_ENC * FEAT];

// ---------------- helpers ----------------
__device__ __forceinline__ u32 smem_u32(const void* p) {
    return (u32)__cvta_generic_to_shared(const_cast<void*>(p));
}
__device__ __forceinline__ void ldsm4(u32* r, u32 addr) {
    asm volatile("ldmatrix.sync.aligned.m8n8.x4.shared.b16 {%0,%1,%2,%3},[%4];"
                 : "=r"(r[0]), "=r"(r[1]), "=r"(r[2]), "=r"(r[3]) : "r"(addr));
}
__device__ __forceinline__ void mma16816(float* c, const u32* a, const u32* b) {
    asm volatile("mma.sync.aligned.m16n8k16.row.col.f32.bf16.bf16.f32 "
                 "{%0,%1,%2,%3},{%4,%5,%6,%7},{%8,%9},{%0,%1,%2,%3};"
                 : "+f"(c[0]), "+f"(c[1]), "+f"(c[2]), "+f"(c[3])
                 : "r"(a[0]), "r"(a[1]), "r"(a[2]), "r"(a[3]), "r"(b[0]), "r"(b[1]));
}
#define CP16(d, s)  asm volatile("cp.async.cg.shared.global [%0], [%1], 16;" :: "r"(d), "l"(s) : "memory")
#define CPCOMMIT()  asm volatile("cp.async.commit_group;" ::: "memory")
#define CPWAIT0()   asm volatile("cp.async.wait_group 0;" ::: "memory")
#define CPWAIT1()   asm volatile("cp.async.wait_group 1;" ::: "memory")
#define CPWAIT2()   asm volatile("cp.async.wait_group 2;" ::: "memory")

__device__ __forceinline__ float sigmoidf_(float x) { return 1.0f / (1.0f + expf(-x)); }

__device__ __forceinline__ void grid_bar(unsigned int* phase) {
    __syncthreads();
    if (threadIdx.x == 0) {
        __threadfence();
        atomicAdd(&g_bar, 1u);
        ++(*phase);
        const unsigned int target = (*phase) * (unsigned int)GRIDSZ;
        for (;;) {
            unsigned int v;
            asm volatile("ld.global.acquire.gpu.u32 %0, [%1];" : "=r"(v) : "l"(&g_bar));
            if (v >= target) break;
            __nanosleep(32);
        }
    }
    __syncthreads();
}

// ---------------- tensor-core GEMM: K=64 chunks, 4-deep, 1 sync/chunk ----------
// 8 warps as 2(m) x 4(n); warp tile m32 x n32. acc[m16-block][n8-frag][4].
__device__ __forceinline__ void gemm_async(float acc[2][4][4], char* smem,
        const __nv_bfloat16* __restrict__ Ah, const __nv_bfloat16* __restrict__ Al,
        size_t lda,
        const __nv_bfloat16* __restrict__ Wh, const __nv_bfloat16* __restrict__ Wl,
        int K, int bm0)
{
    const int tid = threadIdx.x, lane = tid & 31, wid = tid >> 5;
    const int wm = wid & 1, wn = wid >> 1;
    const u32 base = smem_u32(smem);

    // cp.async mapping: 16B seg s -> row s>>3, col16 s&7. 256 thr: A rows r0,r0+32;
    // W rows r0, +32, +64, +96 (per limb).
    const int r0 = tid >> 3;            // 0..31
    const int c8 = (tid & 7) << 3;      // 0..56 elems

    const __nv_bfloat16* gA0 = Ah + (size_t)(bm0 + r0) * lda + c8;
    const __nv_bfloat16* gA1 = Al + (size_t)(bm0 + r0) * lda + c8;
    const __nv_bfloat16* gW0 = Wh + (size_t)r0 * K + c8;
    const __nv_bfloat16* gW1 = Wl + (size_t)r0 * K + c8;
    const size_t a32 = (size_t)32 * lda;
    const size_t w32 = (size_t)32 * K;

    const u32 dA0 = base + (u32)r0 * RPB + (u32)c8 * 2;
    const u32 dA1 = dA0 + A_SZ;
    const u32 dW0 = base + 2 * A_SZ + (u32)r0 * RPB + (u32)c8 * 2;
    const u32 dW1 = dW0 + W_SZ;

    const int nc = K >> 6;

    auto issue = [&](int c) {
        const u32 o = (u32)(c & 3) * CHB;
        const int k0 = c << 6;
        CP16(dA0 + o, gA0 + k0);
        CP16(dA0 + o + 32 * RPB, gA0 + k0 + a32);
        CP16(dA1 + o, gA1 + k0);
        CP16(dA1 + o + 32 * RPB, gA1 + k0 + a32);
#pragma unroll
        for (int k = 0; k < 4; ++k) {
            CP16(dW0 + o + (u32)k * 32 * RPB, gW0 + k0 + (size_t)k * w32);
            CP16(dW1 + o + (u32)k * 32 * RPB, gW1 + k0 + (size_t)k * w32);
        }
        CPCOMMIT();
    };

    // ldmatrix addressing (slot 0 base; add (c&3)*CHB + ks*32 per use)
    const int q = lane >> 3, l7 = lane & 7;
    const int arow = ((q & 1) << 3) + l7, acolb = (q >> 1) << 4;
    const int brow = ((q >> 1) << 3) + l7, bcolb = (q & 1) << 4;
    const u32 aH0 = base + (u32)(wm * 32 + arow) * RPB + acolb;
    const u32 aH1 = aH0 + 16 * RPB;
    const u32 aL0 = aH0 + A_SZ, aL1 = aH1 + A_SZ;
    const u32 bH0 = base + 2 * A_SZ + (u32)(wn * 32 + brow) * RPB + bcolb;
    const u32 bH1 = bH0 + 16 * RPB;
    const u32 bL0 = bH0 + W_SZ, bL1 = bH1 + W_SZ;

    __syncthreads();   // prior smem consumers (gates / previous gemm) done
    issue(0);
    if (1 < nc) issue(1);
    if (2 < nc) issue(2);

    for (int c = 0; c < nc; ++c) {
        if (c + 2 < nc)      { CPWAIT2(); }
        else if (c + 1 < nc) { CPWAIT1(); }
        else                 { CPWAIT0(); }
        __syncthreads();               // publish group c; all done reading c-1
        if (c + 3 < nc) issue(c + 3);  // slot (c+3)&3 == (c-1)&3: free

        const u32 o = (u32)(c & 3) * CHB;
#pragma unroll
        for (int ks = 0; ks < 4; ++ks) {
            const u32 off = o + ks * 32;
            u32 rah0[4], rah1[4], ral0[4], ral1[4];
            u32 rbh0[4], rbh1[4], rbl0[4], rbl1[4];
            ldsm4(rah0, aH0 + off); ldsm4(rah1, aH1 + off);
            ldsm4(ral0, aL0 + off); ldsm4(ral1, aL1 + off);
            ldsm4(rbh0, bH0 + off); ldsm4(rbh1, bH1 + off);
            ldsm4(rbl0, bL0 + off); ldsm4(rbl1, bL1 + off);

            mma16816(acc[0][0], rah0, rbh0); mma16816(acc[0][1], rah0, rbh0 + 2);
            mma16816(acc[0][2], rah0, rbh1); mma16816(acc[0][3], rah0, rbh1 + 2);
            mma16816(acc[1][0], rah1, rbh0); mma16816(acc[1][1], rah1, rbh0 + 2);
            mma16816(acc[1][2], rah1, rbh1); mma16816(acc[1][3], rah1, rbh1 + 2);

            mma16816(acc[0][0], rah0, rbl0); mma16816(acc[0][1], rah0, rbl0 + 2);
            mma16816(acc[0][2], rah0, rbl1); mma16816(acc[0][3], rah0, rbl1 + 2);
            mma16816(acc[1][0], rah1, rbl0); mma16816(acc[1][1], rah1, rbl0 + 2);
            mma16816(acc[1][2], rah1, rbl1); mma16816(acc[1][3], rah1, rbl1 + 2);

            mma16816(acc[0][0], ral0, rbh0); mma16816(acc[0][1], ral0, rbh0 + 2);
            mma16816(acc[0][2], ral0, rbh1); mma16816(acc[0][3], ral0, rbh1 + 2);
            mma16816(acc[1][0], ral1, rbh0); mma16816(acc[1][1], ral1, rbh0 + 2);
            mma16816(acc[1][2], ral1, rbh1); mma16816(acc[1][3], ral1, rbh1 + 2);
        }
    }
}

// ---------------- epilogue: bias + LSTM pointwise (R4 geometry) ----------------
template <int MODE>
__device__ __forceinline__ void epilogue(float acc[2][4][4], char* smem, float cR[8],
                                         const float* __restrict__ b_ih,
                                         const float* __restrict__ b_hh,
                                         __nv_bfloat16* __restrict__ hH,
                                         __nv_bfloat16* __restrict__ hL,
                                         int bm0, int hc0, int tileN,
                                         const float* __restrict__ rank1w,
                                         const float* __restrict__ y,
                                         const int* __restrict__ tf_mask,
                                         float* __restrict__ d_out, int t,
                                         const float* __restrict__ fcW,
                                         const float* __restrict__ fc_b) {
    float (*gates)[BN] = (float (*)[BN])smem;
    const int tid = threadIdx.x;
    const int lane = tid & 31, wid = tid >> 5;
    const int wm = wid & 1, wn = wid >> 1;

    __syncthreads();   // all ldsm reads done before aliasing buffers with gates
    {
        const int r0 = wm * 32 + (lane >> 2);
        const int c0 = wn * 32 + ((lane & 3) << 1);
#pragma unroll
        for (int m = 0; m < 2; ++m)
#pragma unroll
            for (int j = 0; j < 4; ++j) {
                *(float2*)&gates[r0 + m * 16][c0 + j * 8] =
                    make_float2(acc[m][j][0], acc[m][j][1]);
                *(float2*)&gates[r0 + m * 16 + 8][c0 + j * 8] =
                    make_float2(acc[m][j][2], acc[m][j][3]);
            }
    }
    __syncthreads();

    const int pc  = tid & 31;
    const int pr0 = (tid >> 5) * 8;
    const int col = hc0 + pc;

    const float bi = b_ih[col]        + b_hh[col];
    const float bf = b_ih[512 + col]  + b_hh[512 + col];
    const float bg = b_ih[1024 + col] + b_hh[1024 + col];
    const float bo = b_ih[1536 + col] + b_hh[1536 + col];

    float w1i = 0.f, w1f = 0.f, w1g = 0.f, w1o = 0.f, fcw = 0.f;
    if (MODE == 1) {
        w1i = rank1w[col];
        w1f = rank1w[512 + col];
        w1g = rank1w[1024 + col];
        w1o = rank1w[1536 + col];
    }
    if (MODE == 2) fcw = fcW[col];

    const bool tfprev = (MODE == 1 && t > 0) ? (tf_mask[t - 1] != 0) : false;

#pragma unroll
    for (int qq = 0; qq < 8; ++qq) {
        const int r = pr0 + qq;
        const int b = bm0 + r;

        float xi = gates[r][pc]      + bi;
        float xf = gates[r][32 + pc] + bf;
        float xg = gates[r][64 + pc] + bg;
        float xo = gates[r][96 + pc] + bo;

        if (MODE == 1) {
            float din;
            if (t == 0) {
                din = g_dec_in0[b];
            } else {
                float out = fc_b[0];
#pragma unroll
                for (int j = 0; j < 16; ++j) out += g_fc_part[j][b];
                if (tileN == 0 && pc == 0) d_out[b * PRED + (t - 1)] = out;
                din = tfprev ? y[b * PRED + t] : out;
            }
            xi += din * w1i;
            xf += din * w1f;
            xg += din * w1g;
            xo += din * w1o;
        }

        const float ii = sigmoidf_(xi);
        const float ff = sigmoidf_(xf);
        const float gg = tanhf(xg);
        const float oo = sigmoidf_(xo);
        const float c  = ff * cR[qq] + ii * gg;
        cR[qq] = c;
        const float h = oo * tanhf(c);

        __nv_bfloat16 hh = __float2bfloat16(h);
        hH[b * Hd + col] = hh;
        hL[b * Hd + col] = __float2bfloat16(h - __bfloat162float(hh));

        if (MODE == 2) {
            float p = h * fcw;
#pragma unroll
            for (int off = 16; off > 0; off >>= 1)
                p += __shfl_xor_sync(0xFFFFFFFFu, p, off);
            if (pc == 0) g_fc_part[tileN][b] = p;
        }
    }
}

// ---------------- init: split weights/X, zero h (both buffers), seed -----------
__device__ void split_w(__nv_bfloat16* dh, __nv_bfloat16* dl,
                        const float* __restrict__ src, int K, int gid, int stride) {
    const int total = 2048 * K;
    for (int i = gid; i < total; i += stride) {
        const int P = i / K, k = i - P * K;
        const int tn = P >> 7, j = P & 127;
        const int orig = ((j >> 5) << 9) + (tn << 5) + (j & 31);
        const float v = src[orig * K + k];
        const __nv_bfloat16 hh = __float2bfloat16(v);
        dh[i] = hh;
        dl[i] = __float2bfloat16(v - __bfloat162float(hh));
    }
}

__global__ void init_kernel(const float* __restrict__ Xd, const float* __restrict__ Xe,
                            const float* __restrict__ eWi0, const float* __restrict__ eWh0,
                            const float* __restrict__ eWi1, const float* __restrict__ eWh1,
                            const float* __restrict__ dWh0, const float* __restrict__ dWi1,
                            const float* __restrict__ dWh1) {
    const int tid = threadIdx.x;
    const int gid = blockIdx.x * blockDim.x + tid;
    const int stride = gridDim.x * blockDim.x;

    const __nv_bfloat16 z = __float2bfloat16(0.f);
    for (int i = gid; i < Bq * Hd; i += stride) {
        g_h0h[0][i] = z; g_h0h[1][i] = z;
        g_h0l[0][i] = z; g_h0l[1][i] = z;
        g_h1h[0][i] = z; g_h1h[1][i] = z;
        g_h1l[0][i] = z; g_h1l[1][i] = z;
    }
    if (gid == 0) g_bar = 0u;

    {
        const int total = Bq * T_ENC * FEAT;
        for (int i = gid; i < total; i += stride) {
            const float v = Xe[i];
            const __nv_bfloat16 hh = __float2bfloat16(v);
            g_Xh[i] = hh;
            g_Xl[i] = __float2bfloat16(v - __bfloat162float(hh));
        }
    }

    split_w(g_eWh0h, g_eWh0l, eWh0, 512, gid, stride);
    split_w(g_eWi0h, g_eWi0l, eWi0, 128, gid, stride);
    split_w(g_eWi1h, g_eWi1l, eWi1, 512, gid, stride);
    split_w(g_eWh1h, g_eWh1l, eWh1, 512, gid, stride);
    split_w(g_dWh0h, g_dWh0l, dWh0, 512, gid, stride);
    split_w(g_dWi1h, g_dWi1l, dWi1, 512, gid, stride);
    split_w(g_dWh1h, g_dWh1l, dWh1, 512, gid, stride);

    const int b = blockIdx.x;
    if (b < Bq) {
        float s = 0.0f;
        for (int i = tid; i < PRED * 8; i += blockDim.x) s += Xd[b * PRED * 8 + i];
        __shared__ float red[INTHR];
        red[tid] = s;
        __syncthreads();
        for (int off = INTHR / 2; off > 0; off >>= 1) {
            if (tid < off) red[tid] += red[tid + off];
            __syncthreads();
        }
        if (tid == 0) g_dec_in0[b] = red[0];
    }
}

// ---------------- persistent seq2seq kernel ----------------
__global__ __launch_bounds__(NTHR, 1) void seq2seq_kernel(
    const float* __restrict__ y, const int* __restrict__ tfm,
    const float* __restrict__ ebi0, const float* __restrict__ ebh0,
    const float* __restrict__ ebi1, const float* __restrict__ ebh1,
    const float* __restrict__ dWi0,
    const float* __restrict__ dbi0, const float* __restrict__ dbh0,
    const float* __restrict__ dbi1, const float* __restrict__ dbh1,
    const float* __restrict__ fcW, const float* __restrict__ fcB,
    float* __restrict__ d_out) {
    extern __shared__ __align__(128) char s_raw[];

    const int tileM = blockIdx.x >> 4;   // 0..7
    const int tileN = blockIdx.x & 15;   // 0..15
    const int bm0 = tileM * BM;
    const int hc0 = tileN * 32;
    const size_t woff512 = (size_t)tileN * 128 * 512;
    const size_t woff128 = (size_t)tileN * 128 * 128;

    float c0r[8], c1r[8];
#pragma unroll
    for (int qq = 0; qq < 8; ++qq) { c0r[qq] = 0.0f; c1r[qq] = 0.0f; }

    unsigned int phase = 0;
    int par = 0;
    float acc[2][4][4];

#define ZERO_ACC() do { _Pragma("unroll") for (int _m = 0; _m < 2; ++_m) \
    _Pragma("unroll") for (int _j = 0; _j < 4; ++_j) \
    _Pragma("unroll") for (int _k = 0; _k < 4; ++_k) acc[_m][_j][_k] = 0.0f; } while (0)

    // ---------------- encoder (wavefront: layer0(t=s) + layer1(t=s-1)) ----------
    for (int s = 0; s < T_ENC; ++s) {
        const __nv_bfloat16* hr0h = g_h0h[par];
        const __nv_bfloat16* hr0l = g_h0l[par];
        __nv_bfloat16* hw0h = g_h0h[par ^ 1];
        __nv_bfloat16* hw0l = g_h0l[par ^ 1];
        const __nv_bfloat16* hr1h = g_h1h[par];
        const __nv_bfloat16* hr1l = g_h1l[par];
        __nv_bfloat16* hw1h = g_h1h[par ^ 1];
        __nv_bfloat16* hw1l = g_h1l[par ^ 1];

        // layer0(t=s): gates0 = h0(s-1) @ eWh0^T + x_s @ eWi0^T
        ZERO_ACC();
        gemm_async(acc, s_raw, hr0h, hr0l, Hd,
                   g_eWh0h + woff512, g_eWh0l + woff512, 512, bm0);
        gemm_async(acc, s_raw, g_Xh + (size_t)s * FEAT, g_Xl + (size_t)s * FEAT,
                   (size_t)T_ENC * FEAT, g_eWi0h + woff128, g_eWi0l + woff128, 128, bm0);
        epilogue<0>(acc, s_raw, c0r, ebi0, ebh0, hw0h, hw0l, bm0, hc0, tileN,
                    (const float*)0, (const float*)0, (const int*)0, (float*)0, s,
                    (const float*)0, (const float*)0);

        // layer1(t=s-1): gates1 = h0(s-1) @ eWi1^T + h1(s-2) @ eWh1^T
        if (s > 0) {
            ZERO_ACC();
            gemm_async(acc, s_raw, hr0h, hr0l, Hd,
                       g_eWi1h + woff512, g_eWi1l + woff512, 512, bm0);
            gemm_async(acc, s_raw, hr1h, hr1l, Hd,
                       g_eWh1h + woff512, g_eWh1l + woff512, 512, bm0);
            epilogue<0>(acc, s_raw, c1r, ebi1, ebh1, hw1h, hw1l, bm0, hc0, tileN,
                        (const float*)0, (const float*)0, (const int*)0, (float*)0, s,
                        (const float*)0, (const float*)0);
        }
        grid_bar(&phase);
        par ^= 1;
    }

    // tail stage: layer1(t=T_ENC-1), plus copy final h0 across double buffer
    {
        const __nv_bfloat16* hr0h = g_h0h[par];
        const __nv_bfloat16* hr0l = g_h0l[par];
        __nv_bfloat16* hw0h = g_h0h[par ^ 1];
        __nv_bfloat16* hw0l = g_h0l[par ^ 1];
        const __nv_bfloat16* hr1h = g_h1h[par];
        const __nv_bfloat16* hr1l = g_h1l[par];
        __nv_bfloat16* hw1h = g_h1h[par ^ 1];
        __nv_bfloat16* hw1l = g_h1l[par ^ 1];

        ZERO_ACC();
        gemm_async(acc, s_raw, hr0h, hr0l, Hd,
                   g_eWi1h + woff512, g_eWi1l + woff512, 512, bm0);
        gemm_async(acc, s_raw, hr1h, hr1l, Hd,
                   g_eWh1h + woff512, g_eWh1l + woff512, 512, bm0);
        epilogue<0>(acc, s_raw, c1r, ebi1, ebh1, hw1h, hw1l, bm0, hc0, tileN,
                    (const float*)0, (const float*)0, (const int*)0, (float*)0, T_ENC,
                    (const float*)0, (const float*)0);

        for (int i = threadIdx.x; i < BM * 32; i += NTHR) {
            const int r = bm0 + (i >> 5), cc = hc0 + (i & 31);
            hw0h[r * Hd + cc] = hr0h[r * Hd + cc];
            hw0l[r * Hd + cc] = hr0l[r * Hd + cc];
        }
        grid_bar(&phase);
        par ^= 1;
    }

    // ---------------- decoder ----------------
    for (int t = 0; t < PRED; ++t) {
        const __nv_bfloat16* hr0h = g_h0h[par];
        const __nv_bfloat16* hr0l = g_h0l[par];
        __nv_bfloat16* hw0h = g_h0h[par ^ 1];
        __nv_bfloat16* hw0l = g_h0l[par ^ 1];
        const __nv_bfloat16* hr1h = g_h1h[par];
        const __nv_bfloat16* hr1l = g_h1l[par];
        __nv_bfloat16* hw1h = g_h1h[par ^ 1];
        __nv_bfloat16* hw1l = g_h1l[par ^ 1];

        // stage A: gates0 = h0 @ dWh0^T  (+ din * dWi0 in epilogue)
        ZERO_ACC();
        gemm_async(acc, s_raw, hr0h, hr0l, Hd,
                   g_dWh0h + woff512, g_dWh0l + woff512, 512, bm0);
        epilogue<1>(acc, s_raw, c0r, dbi0, dbh0, hw0h, hw0l, bm0, hc0, tileN,
                    dWi0, y, tfm, d_out, t, (const float*)0, fcB);
        grid_bar(&phase);

        // stage B
        ZERO_ACC();
        gemm_async(acc, s_raw, hw0h, hw0l, Hd,
                   g_dWi1h + woff512, g_dWi1l + woff512, 512, bm0);
        gemm_async(acc, s_raw, hr1h, hr1l, Hd,
                   g_dWh1h + woff512, g_dWh1l + woff512, 512, bm0);
        epilogue<2>(acc, s_raw, c1r, dbi1, dbh1, hw1h, hw1l, bm0, hc0, tileN,
                    (const float*)0, (const float*)0, (const int*)0, (float*)0, t,
                    fcW, (const float*)0);
        grid_bar(&phase);
        par ^= 1;
    }

    // ---------------- final output (t = PRED-1) ----------------
    if (tileN == 0 && threadIdx.x < BM) {
        const int b = bm0 + threadIdx.x;
        float out = fcB[0];
#pragma unroll
        for (int j = 0; j < 16; ++j) out += g_fc_part[j][b];
        d_out[b * PRED + (PRED - 1)] = out;
    }
}

// ---------------- harness entry ----------------
extern "C" void kernel_launch(void* const* d_in, const int* in_sizes, int n_in,
                              void* d_out, int out_size) {
    const float* Xe  = (const float*)d_in[0];
    const float* Xd  = (const float*)d_in[1];
    const float* y   = (const float*)d_in[2];
    const int*   tfm = (const int*)d_in[3];
    const float* eWi0 = (const float*)d_in[4];
    const float* eWh0 = (const float*)d_in[5];
    const float* ebi0 = (const float*)d_in[6];
    const float* ebh0 = (const float*)d_in[7];
    const float* eWi1 = (const float*)d_in[8];
    const float* eWh1 = (const float*)d_in[9];
    const float* ebi1 = (const float*)d_in[10];
    const float* ebh1 = (const float*)d_in[11];
    const float* dWi0 = (const float*)d_in[12];
    const float* dWh0 = (const float*)d_in[13];
    const float* dbi0 = (const float*)d_in[14];
    const float* dbh0 = (const float*)d_in[15];
    const float* dWi1 = (const float*)d_in[16];
    const float* dWh1 = (const float*)d_in[17];
    const float* dbi1 = (const float*)d_in[18];
    const float* dbh1 = (const float*)d_in[19];
    const float* fcW  = (const float*)d_in[20];
    const float* fcB  = (const float*)d_in[21];
    float* out = (float*)d_out;

    cudaFuncSetAttribute(seq2seq_kernel,
                         cudaFuncAttributeMaxDynamicSharedMemorySize, SMEM_BYTES);

    init_kernel<<<1024, INTHR>>>(Xd, Xe, eWi0, eWh0, eWi1, eWh1, dWh0, dWi1, dWh1);
    seq2seq_kernel<<<GRIDSZ, NTHR, SMEM_BYTES>>>(y, tfm,
                                                 ebi0, ebh0, ebi1, ebh1,
                                                 dWi0, dbi0, dbh0, dbi1, dbh1,
                                                 fcW, fcB, out);
}

// round 11
// speedup vs baseline: 2.6415x; 1.3094x over previous
#include <cuda_runtime.h>
#include <cuda_fp16.h>
#include <cstdint>
#include <math.h>

typedef unsigned int u32;

// ---------------- problem constants ----------------
#define Bq     512
#define Hd     512
#define FEAT   128
#define T_ENC  512
#define PRED   96

#define GRIDSZ 128
#define NTHR   256            // 8 warps: 2(m) x 4(n), warp tile m32 x n32
#define INTHR  256
#define BM 64
#define BN 128

// ---------------- smem layout (manual, dynamic) ----------------
// chunk (K=64): A[64][144B] Wh[128][144B] Wl[128][144B]
#define RPB   144u            // row pitch bytes (128B payload + 16B pad)
#define A_SZ  9216u           // 64*144
#define W_SZ  18432u          // 128*144
#define CHB   46080u          // A_SZ + 2*W_SZ
#define NBUF  4
#define SMEM_BYTES (NBUF * CHB)   // 184320

// ---------------- persistent device state ----------------
__device__ __half g_h0[2][Bq * Hd];
__device__ __half g_h1[2][Bq * Hd];
__device__ float g_fc_part[16][Bq];
__device__ float g_dec_in0[Bq];
__device__ unsigned int g_bar;

// fp16 split weights, permuted rows: P = tileN*128 + j, orig = (j/32)*512 + tileN*32 + (j%32)
__device__ __half g_eWh0h[2048 * 512], g_eWh0l[2048 * 512];
__device__ __half g_eWi0h[2048 * 128], g_eWi0l[2048 * 128];
__device__ __half g_eWi1h[2048 * 512], g_eWi1l[2048 * 512];
__device__ __half g_eWh1h[2048 * 512], g_eWh1l[2048 * 512];
__device__ __half g_dWh0h[2048 * 512], g_dWh0l[2048 * 512];
__device__ __half g_dWi1h[2048 * 512], g_dWi1l[2048 * 512];
__device__ __half g_dWh1h[2048 * 512], g_dWh1l[2048 * 512];
__device__ __half g_X[Bq * T_ENC * FEAT];

// ---------------- helpers ----------------
__device__ __forceinline__ u32 smem_u32(const void* p) {
    return (u32)__cvta_generic_to_shared(const_cast<void*>(p));
}
__device__ __forceinline__ void ldsm4(u32* r, u32 addr) {
    asm volatile("ldmatrix.sync.aligned.m8n8.x4.shared.b16 {%0,%1,%2,%3},[%4];"
                 : "=r"(r[0]), "=r"(r[1]), "=r"(r[2]), "=r"(r[3]) : "r"(addr));
}
__device__ __forceinline__ void mma16816(float* c, const u32* a, const u32* b) {
    asm volatile("mma.sync.aligned.m16n8k16.row.col.f32.f16.f16.f32 "
                 "{%0,%1,%2,%3},{%4,%5,%6,%7},{%8,%9},{%0,%1,%2,%3};"
                 : "+f"(c[0]), "+f"(c[1]), "+f"(c[2]), "+f"(c[3])
                 : "r"(a[0]), "r"(a[1]), "r"(a[2]), "r"(a[3]), "r"(b[0]), "r"(b[1]));
}
#define CP16(d, s)  asm volatile("cp.async.cg.shared.global [%0], [%1], 16;" :: "r"(d), "l"(s) : "memory")
#define CPCOMMIT()  asm volatile("cp.async.commit_group;" ::: "memory")
#define CPWAIT0()   asm volatile("cp.async.wait_group 0;" ::: "memory")
#define CPWAIT1()   asm volatile("cp.async.wait_group 1;" ::: "memory")
#define CPWAIT2()   asm volatile("cp.async.wait_group 2;" ::: "memory")

__device__ __forceinline__ float sigmoidf_(float x) { return 1.0f / (1.0f + expf(-x)); }

__device__ __forceinline__ void grid_bar(unsigned int* phase) {
    __syncthreads();
    if (threadIdx.x == 0) {
        __threadfence();
        atomicAdd(&g_bar, 1u);
        ++(*phase);
        const unsigned int target = (*phase) * (unsigned int)GRIDSZ;
        for (;;) {
            unsigned int v;
            asm volatile("ld.global.acquire.gpu.u32 %0, [%1];" : "=r"(v) : "l"(&g_bar));
            if (v >= target) break;
            __nanosleep(32);
        }
    }
    __syncthreads();
}

// ---------------- tensor-core GEMM: fp16 2-pass, K=64 chunks, 4-deep -----------
// 8 warps as 2(m) x 4(n); warp tile m32 x n32. acc[m16-block][n8-frag][4].
// gates += A * (Wh + Wl)^T : A single fp16 limb, W dual fp16 limbs.
__device__ __forceinline__ void gemm_async(float acc[2][4][4], char* smem,
        const __half* __restrict__ A, size_t lda,
        const __half* __restrict__ Wh, const __half* __restrict__ Wl,
        int K, int bm0)
{
    const int tid = threadIdx.x, lane = tid & 31, wid = tid >> 5;
    const int wm = wid & 1, wn = wid >> 1;
    const u32 base = smem_u32(smem);

    const int r0 = tid >> 3;            // 0..31
    const int c8 = (tid & 7) << 3;      // 0..56 elems

    const __half* gA  = A + (size_t)(bm0 + r0) * lda + c8;
    const __half* gW0 = Wh + (size_t)r0 * K + c8;
    const __half* gW1 = Wl + (size_t)r0 * K + c8;
    const size_t a32 = (size_t)32 * lda;
    const size_t w32 = (size_t)32 * K;

    const u32 dA  = base + (u32)r0 * RPB + (u32)c8 * 2;
    const u32 dW0 = base + A_SZ + (u32)r0 * RPB + (u32)c8 * 2;
    const u32 dW1 = dW0 + W_SZ;

    const int nc = K >> 6;

    auto issue = [&](int c) {
        const u32 o = (u32)(c & 3) * CHB;
        const int k0 = c << 6;
        CP16(dA + o, gA + k0);
        CP16(dA + o + 32 * RPB, gA + k0 + a32);
#pragma unroll
        for (int k = 0; k < 4; ++k) {
            CP16(dW0 + o + (u32)k * 32 * RPB, gW0 + k0 + (size_t)k * w32);
            CP16(dW1 + o + (u32)k * 32 * RPB, gW1 + k0 + (size_t)k * w32);
        }
        CPCOMMIT();
    };

    // ldmatrix addressing (slot 0 base; add (c&3)*CHB + ks*32 per use)
    const int q = lane >> 3, l7 = lane & 7;
    const int arow = ((q & 1) << 3) + l7, acolb = (q >> 1) << 4;
    const int brow = ((q >> 1) << 3) + l7, bcolb = (q & 1) << 4;
    const u32 aH0 = base + (u32)(wm * 32 + arow) * RPB + acolb;
    const u32 aH1 = aH0 + 16 * RPB;
    const u32 bH0 = base + A_SZ + (u32)(wn * 32 + brow) * RPB + bcolb;
    const u32 bH1 = bH0 + 16 * RPB;
    const u32 bL0 = bH0 + W_SZ, bL1 = bH1 + W_SZ;

    __syncthreads();   // prior smem consumers (gates / previous gemm) done
    issue(0);
    if (1 < nc) issue(1);
    if (2 < nc) issue(2);

    for (int c = 0; c < nc; ++c) {
        if (c + 2 < nc)      { CPWAIT2(); }
        else if (c + 1 < nc) { CPWAIT1(); }
        else                 { CPWAIT0(); }
        __syncthreads();               // publish group c; all done reading c-1
        if (c + 3 < nc) issue(c + 3);  // slot (c+3)&3 == (c-1)&3: free

        const u32 o = (u32)(c & 3) * CHB;
#pragma unroll
        for (int ks = 0; ks < 4; ++ks) {
            const u32 off = o + ks * 32;
            u32 rah0[4], rah1[4];
            u32 rbh0[4], rbh1[4], rbl0[4], rbl1[4];
            ldsm4(rah0, aH0 + off); ldsm4(rah1, aH1 + off);
            ldsm4(rbh0, bH0 + off); ldsm4(rbh1, bH1 + off);
            ldsm4(rbl0, bL0 + off); ldsm4(rbl1, bL1 + off);

            mma16816(acc[0][0], rah0, rbh0); mma16816(acc[0][1], rah0, rbh0 + 2);
            mma16816(acc[0][2], rah0, rbh1); mma16816(acc[0][3], rah0, rbh1 + 2);
            mma16816(acc[1][0], rah1, rbh0); mma16816(acc[1][1], rah1, rbh0 + 2);
            mma16816(acc[1][2], rah1, rbh1); mma16816(acc[1][3], rah1, rbh1 + 2);

            mma16816(acc[0][0], rah0, rbl0); mma16816(acc[0][1], rah0, rbl0 + 2);
            mma16816(acc[0][2], rah0, rbl1); mma16816(acc[0][3], rah0, rbl1 + 2);
            mma16816(acc[1][0], rah1, rbl0); mma16816(acc[1][1], rah1, rbl0 + 2);
            mma16816(acc[1][2], rah1, rbl1); mma16816(acc[1][3], rah1, rbl1 + 2);
        }
    }
}

// ---------------- epilogue: bias + LSTM pointwise ------------------------------
template <int MODE>
__device__ __forceinline__ void epilogue(float acc[2][4][4], char* smem, float cR[8],
                                         const float* __restrict__ b_ih,
                                         const float* __restrict__ b_hh,
                                         __half* __restrict__ hOut,
                                         int bm0, int hc0, int tileN,
                                         const float* __restrict__ rank1w,
                                         const float* __restrict__ y,
                                         const int* __restrict__ tf_mask,
                                         float* __restrict__ d_out, int t,
                                         const float* __restrict__ fcW,
                                         const float* __restrict__ fc_b) {
    float (*gates)[BN] = (float (*)[BN])smem;
    const int tid = threadIdx.x;
    const int lane = tid & 31, wid = tid >> 5;
    const int wm = wid & 1, wn = wid >> 1;

    __syncthreads();   // all ldsm reads done before aliasing buffers with gates
    {
        const int r0 = wm * 32 + (lane >> 2);
        const int c0 = wn * 32 + ((lane & 3) << 1);
#pragma unroll
        for (int m = 0; m < 2; ++m)
#pragma unroll
            for (int j = 0; j < 4; ++j) {
                *(float2*)&gates[r0 + m * 16][c0 + j * 8] =
                    make_float2(acc[m][j][0], acc[m][j][1]);
                *(float2*)&gates[r0 + m * 16 + 8][c0 + j * 8] =
                    make_float2(acc[m][j][2], acc[m][j][3]);
            }
    }
    __syncthreads();

    const int pc  = tid & 31;
    const int pr0 = (tid >> 5) * 8;
    const int col = hc0 + pc;

    const float bi = b_ih[col]        + b_hh[col];
    const float bf = b_ih[512 + col]  + b_hh[512 + col];
    const float bg = b_ih[1024 + col] + b_hh[1024 + col];
    const float bo = b_ih[1536 + col] + b_hh[1536 + col];

    float w1i = 0.f, w1f = 0.f, w1g = 0.f, w1o = 0.f, fcw = 0.f;
    if (MODE == 1) {
        w1i = rank1w[col];
        w1f = rank1w[512 + col];
        w1g = rank1w[1024 + col];
        w1o = rank1w[1536 + col];
    }
    if (MODE == 2) fcw = fcW[col];

    const bool tfprev = (MODE == 1 && t > 0) ? (tf_mask[t - 1] != 0) : false;

#pragma unroll
    for (int qq = 0; qq < 8; ++qq) {
        const int r = pr0 + qq;
        const int b = bm0 + r;

        float xi = gates[r][pc]      + bi;
        float xf = gates[r][32 + pc] + bf;
        float xg = gates[r][64 + pc] + bg;
        float xo = gates[r][96 + pc] + bo;

        if (MODE == 1) {
            float din;
            if (t == 0) {
                din = g_dec_in0[b];
            } else {
                float out = fc_b[0];
#pragma unroll
                for (int j = 0; j < 16; ++j) out += g_fc_part[j][b];
                if (tileN == 0 && pc == 0) d_out[b * PRED + (t - 1)] = out;
                din = tfprev ? y[b * PRED + t] : out;
            }
            xi += din * w1i;
            xf += din * w1f;
            xg += din * w1g;
            xo += din * w1o;
        }

        const float ii = sigmoidf_(xi);
        const float ff = sigmoidf_(xf);
        const float gg = tanhf(xg);
        const float oo = sigmoidf_(xo);
        const float c  = ff * cR[qq] + ii * gg;
        cR[qq] = c;
        const float h = oo * tanhf(c);

        hOut[b * Hd + col] = __float2half(h);

        if (MODE == 2) {
            float p = h * fcw;
#pragma unroll
            for (int off = 16; off > 0; off >>= 1)
                p += __shfl_xor_sync(0xFFFFFFFFu, p, off);
            if (pc == 0) g_fc_part[tileN][b] = p;
        }
    }
}

// ---------------- init: split weights (fp16 hi/lo), X fp16, zero h, seed -------
__device__ void split_w(__half* dh, __half* dl,
                        const float* __restrict__ src, int K, int gid, int stride) {
    const int total = 2048 * K;
    for (int i = gid; i < total; i += stride) {
        const int P = i / K, k = i - P * K;
        const int tn = P >> 7, j = P & 127;
        const int orig = ((j >> 5) << 9) + (tn << 5) + (j & 31);
        const float v = src[orig * K + k];
        const __half hh = __float2half_rn(v);
        dh[i] = hh;
        dl[i] = __float2half_rn(v - __half2float(hh));
    }
}

__global__ void init_kernel(const float* __restrict__ Xd, const float* __restrict__ Xe,
                            const float* __restrict__ eWi0, const float* __restrict__ eWh0,
                            const float* __restrict__ eWi1, const float* __restrict__ eWh1,
                            const float* __restrict__ dWh0, const float* __restrict__ dWi1,
                            const float* __restrict__ dWh1) {
    const int tid = threadIdx.x;
    const int gid = blockIdx.x * blockDim.x + tid;
    const int stride = gridDim.x * blockDim.x;

    const __half z = __float2half(0.f);
    for (int i = gid; i < Bq * Hd; i += stride) {
        g_h0[0][i] = z; g_h0[1][i] = z;
        g_h1[0][i] = z; g_h1[1][i] = z;
    }
    if (gid == 0) g_bar = 0u;

    {
        const int total = Bq * T_ENC * FEAT;
        for (int i = gid; i < total; i += stride)
            g_X[i] = __float2half_rn(Xe[i]);
    }

    split_w(g_eWh0h, g_eWh0l, eWh0, 512, gid, stride);
    split_w(g_eWi0h, g_eWi0l, eWi0, 128, gid, stride);
    split_w(g_eWi1h, g_eWi1l, eWi1, 512, gid, stride);
    split_w(g_eWh1h, g_eWh1l, eWh1, 512, gid, stride);
    split_w(g_dWh0h, g_dWh0l, dWh0, 512, gid, stride);
    split_w(g_dWi1h, g_dWi1l, dWi1, 512, gid, stride);
    split_w(g_dWh1h, g_dWh1l, dWh1, 512, gid, stride);

    const int b = blockIdx.x;
    if (b < Bq) {
        float s = 0.0f;
        for (int i = tid; i < PRED * 8; i += blockDim.x) s += Xd[b * PRED * 8 + i];
        __shared__ float red[INTHR];
        red[tid] = s;
        __syncthreads();
        for (int off = INTHR / 2; off > 0; off >>= 1) {
            if (tid < off) red[tid] += red[tid + off];
            __syncthreads();
        }
        if (tid == 0) g_dec_in0[b] = red[0];
    }
}

// ---------------- persistent seq2seq kernel ----------------
__global__ __launch_bounds__(NTHR, 1) void seq2seq_kernel(
    const float* __restrict__ y, const int* __restrict__ tfm,
    const float* __restrict__ ebi0, const float* __restrict__ ebh0,
    const float* __restrict__ ebi1, const float* __restrict__ ebh1,
    const float* __restrict__ dWi0,
    const float* __restrict__ dbi0, const float* __restrict__ dbh0,
    const float* __restrict__ dbi1, const float* __restrict__ dbh1,
    const float* __restrict__ fcW, const float* __restrict__ fcB,
    float* __restrict__ d_out) {
    extern __shared__ __align__(128) char s_raw[];

    const int tileM = blockIdx.x >> 4;   // 0..7
    const int tileN = blockIdx.x & 15;   // 0..15
    const int bm0 = tileM * BM;
    const int hc0 = tileN * 32;
    const size_t woff512 = (size_t)tileN * 128 * 512;
    const size_t woff128 = (size_t)tileN * 128 * 128;

    float c0r[8], c1r[8];
#pragma unroll
    for (int qq = 0; qq < 8; ++qq) { c0r[qq] = 0.0f; c1r[qq] = 0.0f; }

    unsigned int phase = 0;
    int par = 0;
    float acc[2][4][4];

#define ZERO_ACC() do { _Pragma("unroll") for (int _m = 0; _m < 2; ++_m) \
    _Pragma("unroll") for (int _j = 0; _j < 4; ++_j) \
    _Pragma("unroll") for (int _k = 0; _k < 4; ++_k) acc[_m][_j][_k] = 0.0f; } while (0)

    // ---------------- encoder (wavefront: layer0(t=s) + layer1(t=s-1)) ----------
    for (int s = 0; s < T_ENC; ++s) {
        const __half* hr0 = g_h0[par];
        __half* hw0 = g_h0[par ^ 1];
        const __half* hr1 = g_h1[par];
        __half* hw1 = g_h1[par ^ 1];

        // layer0(t=s): gates0 = h0(s-1) @ eWh0^T + x_s @ eWi0^T
        ZERO_ACC();
        gemm_async(acc, s_raw, hr0, Hd,
                   g_eWh0h + woff512, g_eWh0l + woff512, 512, bm0);
        gemm_async(acc, s_raw, g_X + (size_t)s * FEAT, (size_t)T_ENC * FEAT,
                   g_eWi0h + woff128, g_eWi0l + woff128, 128, bm0);
        epilogue<0>(acc, s_raw, c0r, ebi0, ebh0, hw0, bm0, hc0, tileN,
                    (const float*)0, (const float*)0, (const int*)0, (float*)0, s,
                    (const float*)0, (const float*)0);

        // layer1(t=s-1): gates1 = h0(s-1) @ eWi1^T + h1(s-2) @ eWh1^T
        if (s > 0) {
            ZERO_ACC();
            gemm_async(acc, s_raw, hr0, Hd,
                       g_eWi1h + woff512, g_eWi1l + woff512, 512, bm0);
            gemm_async(acc, s_raw, hr1, Hd,
                       g_eWh1h + woff512, g_eWh1l + woff512, 512, bm0);
            epilogue<0>(acc, s_raw, c1r, ebi1, ebh1, hw1, bm0, hc0, tileN,
                        (const float*)0, (const float*)0, (const int*)0, (float*)0, s,
                        (const float*)0, (const float*)0);
        }
        grid_bar(&phase);
        par ^= 1;
    }

    // tail stage: layer1(t=T_ENC-1), plus copy final h0 across double buffer
    {
        const __half* hr0 = g_h0[par];
        __half* hw0 = g_h0[par ^ 1];
        const __half* hr1 = g_h1[par];
        __half* hw1 = g_h1[par ^ 1];

        ZERO_ACC();
        gemm_async(acc, s_raw, hr0, Hd,
                   g_eWi1h + woff512, g_eWi1l + woff512, 512, bm0);
        gemm_async(acc, s_raw, hr1, Hd,
                   g_eWh1h + woff512, g_eWh1l + woff512, 512, bm0);
        epilogue<0>(acc, s_raw, c1r, ebi1, ebh1, hw1, bm0, hc0, tileN,
                    (const float*)0, (const float*)0, (const int*)0, (float*)0, T_ENC,
                    (const float*)0, (const float*)0);

        for (int i = threadIdx.x; i < BM * 32; i += NTHR) {
            const int r = bm0 + (i >> 5), cc = hc0 + (i & 31);
            hw0[r * Hd + cc] = hr0[r * Hd + cc];
        }
        grid_bar(&phase);
        par ^= 1;
    }

    // ---------------- decoder ----------------
    for (int t = 0; t < PRED; ++t) {
        const __half* hr0 = g_h0[par];
        __half* hw0 = g_h0[par ^ 1];
        const __half* hr1 = g_h1[par];
        __half* hw1 = g_h1[par ^ 1];

        // stage A: gates0 = h0 @ dWh0^T  (+ din * dWi0 in epilogue)
        ZERO_ACC();
        gemm_async(acc, s_raw, hr0, Hd,
                   g_dWh0h + woff512, g_dWh0l + woff512, 512, bm0);
        epilogue<1>(acc, s_raw, c0r, dbi0, dbh0, hw0, bm0, hc0, tileN,
                    dWi0, y, tfm, d_out, t, (const float*)0, fcB);
        grid_bar(&phase);

        // stage B
        ZERO_ACC();
        gemm_async(acc, s_raw, hw0, Hd,
                   g_dWi1h + woff512, g_dWi1l + woff512, 512, bm0);
        gemm_async(acc, s_raw, hr1, Hd,
                   g_dWh1h + woff512, g_dWh1l + woff512, 512, bm0);
        epilogue<2>(acc, s_raw, c1r, dbi1, dbh1, hw1, bm0, hc0, tileN,
                    (const float*)0, (const float*)0, (const int*)0, (float*)0, t,
                    fcW, (const float*)0);
        grid_bar(&phase);
        par ^= 1;
    }

    // ---------------- final output (t = PRED-1) ----------------
    if (tileN == 0 && threadIdx.x < BM) {
        const int b = bm0 + threadIdx.x;
        float out = fcB[0];
#pragma unroll
        for (int j = 0; j < 16; ++j) out += g_fc_part[j][b];
        d_out[b * PRED + (PRED - 1)] = out;
    }
}

// ---------------- harness entry ----------------
extern "C" void kernel_launch(void* const* d_in, const int* in_sizes, int n_in,
                              void* d_out, int out_size) {
    const float* Xe  = (const float*)d_in[0];
    const float* Xd  = (const float*)d_in[1];
    const float* y   = (const float*)d_in[2];
    const int*   tfm = (const int*)d_in[3];
    const float* eWi0 = (const float*)d_in[4];
    const float* eWh0 = (const float*)d_in[5];
    const float* ebi0 = (const float*)d_in[6];
    const float* ebh0 = (const float*)d_in[7];
    const float* eWi1 = (const float*)d_in[8];
    const float* eWh1 = (const float*)d_in[9];
    const float* ebi1 = (const float*)d_in[10];
    const float* ebh1 = (const float*)d_in[11];
    const float* dWi0 = (const float*)d_in[12];
    const float* dWh0 = (const float*)d_in[13];
    const float* dbi0 = (const float*)d_in[14];
    const float* dbh0 = (const float*)d_in[15];
    const float* dWi1 = (const float*)d_in[16];
    const float* dWh1 = (const float*)d_in[17];
    const float* dbi1 = (const float*)d_in[18];
    const float* dbh1 = (const float*)d_in[19];
    const float* fcW  = (const float*)d_in[20];
    const float* fcB  = (const float*)d_in[21];
    float* out = (float*)d_out;

    cudaFuncSetAttribute(seq2seq_kernel,
                         cudaFuncAttributeMaxDynamicSharedMemorySize, SMEM_BYTES);

    init_kernel<<<1024, INTHR>>>(Xd, Xe, eWi0, eWh0, eWi1, eWh1, dWh0, dWi1, dWh1);
    seq2seq_kernel<<<GRIDSZ, NTHR, SMEM_BYTES>>>(y, tfm,
                                                 ebi0, ebh0, ebi1, ebh1,
                                                 dWi0, dbi0, dbh0, dbi1, dbh1,
                                                 fcW, fcB, out);
}

// round 13
// speedup vs baseline: 2.8009x; 1.0603x over previous
#include <cuda_runtime.h>
#include <cuda_fp16.h>
#include <cstdint>
#include <math.h>

typedef unsigned int u32;

// ---------------- problem constants ----------------
#define Bq     512
#define Hd     512
#define FEAT   128
#define T_ENC  512
#define PRED   96

#define GRIDSZ 128
#define NTHR   256            // 8 warps: 2(m) x 4(n), warp tile m32 x n32
#define INTHR  256
#define BM 64
#define BN 128

// ---------------- smem layout (manual, dynamic) ----------------
// chunk (K=64): A[64][144B] Wh[128][144B] Wl[128][144B]
#define RPB   144u
#define A_SZ  9216u            // 64*144
#define W_SZ  18432u           // 128*144
#define CHB   46080u           // A_SZ + 2*W_SZ
#define NBUF  4
#define GATES_OFF (NBUF * CHB)            // 184320
#define SMEM_BYTES (GATES_OFF + BM * BN * 4)  // 217088

// ---------------- persistent device state ----------------
__device__ __half g_h0[2][Bq * Hd];
__device__ __half g_h1[2][Bq * Hd];
__device__ float g_fc_part[16][Bq];
__device__ float g_dec_in0[Bq];
__device__ unsigned int g_bar;

// fp16 split weights, permuted rows: P = tileN*128 + j, orig = (j/32)*512 + tileN*32 + (j%32)
__device__ __half g_eWh0h[2048 * 512], g_eWh0l[2048 * 512];
__device__ __half g_eWi0h[2048 * 128], g_eWi0l[2048 * 128];
__device__ __half g_eWi1h[2048 * 512], g_eWi1l[2048 * 512];
__device__ __half g_eWh1h[2048 * 512], g_eWh1l[2048 * 512];
__device__ __half g_dWh0h[2048 * 512], g_dWh0l[2048 * 512];
__device__ __half g_dWi1h[2048 * 512], g_dWi1l[2048 * 512];
__device__ __half g_dWh1h[2048 * 512], g_dWh1l[2048 * 512];
__device__ __half g_X[Bq * T_ENC * FEAT];

// ---------------- helpers ----------------
__device__ __forceinline__ u32 smem_u32(const void* p) {
    return (u32)__cvta_generic_to_shared(const_cast<void*>(p));
}
__device__ __forceinline__ void ldsm4(u32* r, u32 addr) {
    asm volatile("ldmatrix.sync.aligned.m8n8.x4.shared.b16 {%0,%1,%2,%3},[%4];"
                 : "=r"(r[0]), "=r"(r[1]), "=r"(r[2]), "=r"(r[3]) : "r"(addr));
}
__device__ __forceinline__ void mma16816(float* c, const u32* a, const u32* b) {
    asm volatile("mma.sync.aligned.m16n8k16.row.col.f32.f16.f16.f32 "
                 "{%0,%1,%2,%3},{%4,%5,%6,%7},{%8,%9},{%0,%1,%2,%3};"
                 : "+f"(c[0]), "+f"(c[1]), "+f"(c[2]), "+f"(c[3])
                 : "r"(a[0]), "r"(a[1]), "r"(a[2]), "r"(a[3]), "r"(b[0]), "r"(b[1]));
}
#define CP16(d, s)  asm volatile("cp.async.cg.shared.global [%0], [%1], 16;" :: "r"(d), "l"(s) : "memory")
#define CPCOMMIT()  asm volatile("cp.async.commit_group;" ::: "memory")
#define CPWAIT0()   asm volatile("cp.async.wait_group 0;" ::: "memory")
#define CPWAIT1()   asm volatile("cp.async.wait_group 1;" ::: "memory")
#define CPWAIT2()   asm volatile("cp.async.wait_group 2;" ::: "memory")

__device__ __forceinline__ float sigmoid_fast(float x) {
    return __fdividef(1.0f, 1.0f + __expf(-x));
}
__device__ __forceinline__ float tanh_fast(float x) {
    const float t = __expf(-2.0f * fabsf(x));
    const float r = __fdividef(1.0f - t, 1.0f + t);
    return x < 0.0f ? -r : r;
}

__device__ __forceinline__ void grid_bar(unsigned int* phase) {
    __syncthreads();
    if (threadIdx.x == 0) {
        __threadfence();
        atomicAdd(&g_bar, 1u);
        ++(*phase);
        const unsigned int target = (*phase) * (unsigned int)GRIDSZ;
        for (;;) {
            unsigned int v;
            asm volatile("ld.global.acquire.gpu.u32 %0, [%1];" : "=r"(v) : "l"(&g_bar));
            if (v >= target) break;
            __nanosleep(32);
        }
    }
    __syncthreads();
}

// ---------------- fused multi-segment tensor-core GEMM pipeline -----------------
// Up to 4 segments stream through one 4-deep cp.async pipeline; chunks < accSplit
// accumulate into acc0, the rest into acc1. fp16 2-pass (W hi/lo, A single limb).
// Segment W strides are FIXED: seg0=512, seg1=128 (X@Wi0 only), seg2=512, seg3=512.
// 8 warps as 2(m) x 4(n); warp tile m32 x n32.
__device__ __forceinline__ void gemm_pipe(
        float acc0[2][4][4], float acc1[2][4][4], char* smem,
        const __half* A0, size_t lda0, const __half* W0h, const __half* W0l, int nc0,
        const __half* A1, size_t lda1, const __half* W1h, const __half* W1l, int nc1,
        const __half* A2, size_t lda2, const __half* W2h, const __half* W2l, int nc2,
        const __half* A3, size_t lda3, const __half* W3h, const __half* W3l, int nc3,
        int accSplit, int bm0)
{
    const int tid = threadIdx.x, lane = tid & 31, wid = tid >> 5;
    const int wm = wid & 1, wn = wid >> 1;
    const u32 base = smem_u32(smem);

    const int r0 = tid >> 3;            // 0..31
    const int c8 = (tid & 7) << 3;      // 0..56 elems

    // per-segment global pointers for this thread's cp.async lanes
    const __half* gA0 = A0 + (size_t)(bm0 + r0) * lda0 + c8;
    const __half* gA1 = A1 ? A1 + (size_t)(bm0 + r0) * lda1 + c8 : gA0;
    const __half* gA2 = A2 ? A2 + (size_t)(bm0 + r0) * lda2 + c8 : gA0;
    const __half* gA3 = A3 ? A3 + (size_t)(bm0 + r0) * lda3 + c8 : gA0;
    const size_t a0s = (size_t)32 * lda0, a1s = (size_t)32 * lda1;
    const size_t a2s = (size_t)32 * lda2, a3s = (size_t)32 * lda3;

    const __half* gW0h = W0h + (size_t)r0 * 512 + c8;
    const __half* gW0l = W0l + (size_t)r0 * 512 + c8;
    const __half* gW1h = W1h ? W1h + (size_t)r0 * 128 + c8 : gW0h; // seg1 = X@Wi0 (K=128)
    const __half* gW1l = W1l ? W1l + (size_t)r0 * 128 + c8 : gW0l;
    const __half* gW2h = W2h ? W2h + (size_t)r0 * 512 + c8 : gW0h;
    const __half* gW2l = W2l ? W2l + (size_t)r0 * 512 + c8 : gW0l;
    const __half* gW3h = W3h ? W3h + (size_t)r0 * 512 + c8 : gW0h;
    const __half* gW3l = W3l ? W3l + (size_t)r0 * 512 + c8 : gW0l;
    const size_t w512 = (size_t)32 * 512, w128 = (size_t)32 * 128;

    const u32 dA  = base + (u32)r0 * RPB + (u32)c8 * 2;
    const u32 dW0 = base + A_SZ + (u32)r0 * RPB + (u32)c8 * 2;
    const u32 dW1 = dW0 + W_SZ;

    const int e0 = nc0, e1 = e0 + nc1, e2 = e1 + nc2, e3 = e2 + nc3;
    const int nc = e3;

#define ISSUE_SEG(cl, GA, AS, GWH, GWL, WS, O) do { \
        const int _k0 = (cl) << 6; \
        CP16(dA + (O), (GA) + _k0); \
        CP16(dA + (O) + 32 * RPB, (GA) + _k0 + (AS)); \
        _Pragma("unroll") \
        for (int _k = 0; _k < 4; ++_k) { \
            CP16(dW0 + (O) + (u32)_k * 32 * RPB, (GWH) + _k0 + (size_t)_k * (WS)); \
            CP16(dW1 + (O) + (u32)_k * 32 * RPB, (GWL) + _k0 + (size_t)_k * (WS)); \
        } \
        CPCOMMIT(); \
    } while (0)

    auto issue = [&](int c) {
        const u32 o = (u32)(c & 3) * CHB;
        if (c < e0)      ISSUE_SEG(c,      gA0, a0s, gW0h, gW0l, w512, o);
        else if (c < e1) ISSUE_SEG(c - e0, gA1, a1s, gW1h, gW1l, w128, o);
        else if (c < e2) ISSUE_SEG(c - e1, gA2, a2s, gW2h, gW2l, w512, o);
        else             ISSUE_SEG(c - e2, gA3, a3s, gW3h, gW3l, w512, o);
    };

    // ldmatrix addressing (slot 0 base; add (c&3)*CHB + ks*32 per use)
    const int q = lane >> 3, l7 = lane & 7;
    const int arow = ((q & 1) << 3) + l7, acolb = (q >> 1) << 4;
    const int brow = ((q >> 1) << 3) + l7, bcolb = (q & 1) << 4;
    const u32 aH0 = base + (u32)(wm * 32 + arow) * RPB + acolb;
    const u32 aH1 = aH0 + 16 * RPB;
    const u32 bH0 = base + A_SZ + (u32)(wn * 32 + brow) * RPB + bcolb;
    const u32 bH1 = bH0 + 16 * RPB;
    const u32 bL0 = bH0 + W_SZ, bL1 = bH1 + W_SZ;

#define CHUNK_MMA(ACC, O) do { \
        _Pragma("unroll") \
        for (int _ks = 0; _ks < 4; ++_ks) { \
            const u32 _off = (O) + _ks * 32; \
            u32 _rah0[4], _rah1[4]; \
            u32 _rbh0[4], _rbh1[4], _rbl0[4], _rbl1[4]; \
            ldsm4(_rah0, aH0 + _off); ldsm4(_rah1, aH1 + _off); \
            ldsm4(_rbh0, bH0 + _off); ldsm4(_rbh1, bH1 + _off); \
            ldsm4(_rbl0, bL0 + _off); ldsm4(_rbl1, bL1 + _off); \
            mma16816((ACC)[0][0], _rah0, _rbh0); mma16816((ACC)[0][1], _rah0, _rbh0 + 2); \
            mma16816((ACC)[0][2], _rah0, _rbh1); mma16816((ACC)[0][3], _rah0, _rbh1 + 2); \
            mma16816((ACC)[1][0], _rah1, _rbh0); mma16816((ACC)[1][1], _rah1, _rbh0 + 2); \
            mma16816((ACC)[1][2], _rah1, _rbh1); mma16816((ACC)[1][3], _rah1, _rbh1 + 2); \
            mma16816((ACC)[0][0], _rah0, _rbl0); mma16816((ACC)[0][1], _rah0, _rbl0 + 2); \
            mma16816((ACC)[0][2], _rah0, _rbl1); mma16816((ACC)[0][3], _rah0, _rbl1 + 2); \
            mma16816((ACC)[1][0], _rah1, _rbl0); mma16816((ACC)[1][1], _rah1, _rbl0 + 2); \
            mma16816((ACC)[1][2], _rah1, _rbl1); mma16816((ACC)[1][3], _rah1, _rbl1 + 2); \
        } \
    } while (0)

    __syncthreads();   // prior chunk-buffer consumers done
    issue(0);
    if (1 < nc) issue(1);
    if (2 < nc) issue(2);

    for (int c = 0; c < nc; ++c) {
        if (c + 2 < nc)      { CPWAIT2(); }
        else if (c + 1 < nc) { CPWAIT1(); }
        else                 { CPWAIT0(); }
        __syncthreads();               // publish group c; all done reading c-1
        if (c + 3 < nc) issue(c + 3);  // slot (c+3)&3 == (c-1)&3: free

        const u32 o = (u32)(c & 3) * CHB;
        if (c < accSplit) { CHUNK_MMA(acc0, o); }
        else              { CHUNK_MMA(acc1, o); }
    }
}

// ---------------- epilogue: bias + LSTM pointwise ------------------------------
template <int MODE>
__device__ __forceinline__ void epilogue(float acc[2][4][4], char* smem, float cR[8],
                                         const float* __restrict__ b_ih,
                                         const float* __restrict__ b_hh,
                                         __half* __restrict__ hOut,
                                         int bm0, int hc0, int tileN,
                                         const float* __restrict__ rank1w,
                                         const float* __restrict__ y,
                                         const int* __restrict__ tf_mask,
                                         float* __restrict__ d_out, int t,
                                         const float* __restrict__ fcW,
                                         const float* __restrict__ fc_b) {
    float (*gates)[BN] = (float (*)[BN])(smem + GATES_OFF);
    const int tid = threadIdx.x;
    const int lane = tid & 31, wid = tid >> 5;
    const int wm = wid & 1, wn = wid >> 1;

    __syncthreads();   // previous epilogue's gates reads done
    {
        const int r0 = wm * 32 + (lane >> 2);
        const int c0 = wn * 32 + ((lane & 3) << 1);
#pragma unroll
        for (int m = 0; m < 2; ++m)
#pragma unroll
            for (int j = 0; j < 4; ++j) {
                *(float2*)&gates[r0 + m * 16][c0 + j * 8] =
                    make_float2(acc[m][j][0], acc[m][j][1]);
                *(float2*)&gates[r0 + m * 16 + 8][c0 + j * 8] =
                    make_float2(acc[m][j][2], acc[m][j][3]);
            }
    }
    __syncthreads();

    const int pc  = tid & 31;
    const int pr0 = (tid >> 5) * 8;
    const int col = hc0 + pc;

    const float bi = b_ih[col]        + b_hh[col];
    const float bf = b_ih[512 + col]  + b_hh[512 + col];
    const float bg = b_ih[1024 + col] + b_hh[1024 + col];
    const float bo = b_ih[1536 + col] + b_hh[1536 + col];

    float w1i = 0.f, w1f = 0.f, w1g = 0.f, w1o = 0.f, fcw = 0.f;
    if (MODE == 1) {
        w1i = rank1w[col];
        w1f = rank1w[512 + col];
        w1g = rank1w[1024 + col];
        w1o = rank1w[1536 + col];
    }
    if (MODE == 2) fcw = fcW[col];

    const bool tfprev = (MODE == 1 && t > 0) ? (tf_mask[t - 1] != 0) : false;

#pragma unroll
    for (int qq = 0; qq < 8; ++qq) {
        const int r = pr0 + qq;
        const int b = bm0 + r;

        float xi = gates[r][pc]      + bi;
        float xf = gates[r][32 + pc] + bf;
        float xg = gates[r][64 + pc] + bg;
        float xo = gates[r][96 + pc] + bo;

        if (MODE == 1) {
            float din;
            if (t == 0) {
                din = g_dec_in0[b];
            } else {
                float out = fc_b[0];
#pragma unroll
                for (int j = 0; j < 16; ++j) out += g_fc_part[j][b];
                if (tileN == 0 && pc == 0) d_out[b * PRED + (t - 1)] = out;
                din = tfprev ? y[b * PRED + t] : out;
            }
            xi += din * w1i;
            xf += din * w1f;
            xg += din * w1g;
            xo += din * w1o;
        }

        const float ii = sigmoid_fast(xi);
        const float ff = sigmoid_fast(xf);
        const float gg = tanh_fast(xg);
        const float oo = sigmoid_fast(xo);
        const float c  = ff * cR[qq] + ii * gg;
        cR[qq] = c;
        const float h = oo * tanh_fast(c);

        hOut[b * Hd + col] = __float2half(h);

        if (MODE == 2) {
            float p = h * fcw;
#pragma unroll
            for (int off = 16; off > 0; off >>= 1)
                p += __shfl_xor_sync(0xFFFFFFFFu, p, off);
            if (pc == 0) g_fc_part[tileN][b] = p;
        }
    }
}

// ---------------- init: split weights (fp16 hi/lo), X fp16, zero h, seed -------
__device__ void split_w(__half* dh, __half* dl,
                        const float* __restrict__ src, int K, int gid, int stride) {
    const int total = 2048 * K;
    for (int i = gid; i < total; i += stride) {
        const int P = i / K, k = i - P * K;
        const int tn = P >> 7, j = P & 127;
        const int orig = ((j >> 5) << 9) + (tn << 5) + (j & 31);
        const float v = src[orig * K + k];
        const __half hh = __float2half_rn(v);
        dh[i] = hh;
        dl[i] = __float2half_rn(v - __half2float(hh));
    }
}

__global__ void init_kernel(const float* __restrict__ Xd, const float* __restrict__ Xe,
                            const float* __restrict__ eWi0, const float* __restrict__ eWh0,
                            const float* __restrict__ eWi1, const float* __restrict__ eWh1,
                            const float* __restrict__ dWh0, const float* __restrict__ dWi1,
                            const float* __restrict__ dWh1) {
    const int tid = threadIdx.x;
    const int gid = blockIdx.x * blockDim.x + tid;
    const int stride = gridDim.x * blockDim.x;

    const __half z = __float2half(0.f);
    for (int i = gid; i < Bq * Hd; i += stride) {
        g_h0[0][i] = z; g_h0[1][i] = z;
        g_h1[0][i] = z; g_h1[1][i] = z;
    }
    if (gid == 0) g_bar = 0u;

    {
        const int total = Bq * T_ENC * FEAT;
        for (int i = gid; i < total; i += stride)
            g_X[i] = __float2half_rn(Xe[i]);
    }

    split_w(g_eWh0h, g_eWh0l, eWh0, 512, gid, stride);
    split_w(g_eWi0h, g_eWi0l, eWi0, 128, gid, stride);
    split_w(g_eWi1h, g_eWi1l, eWi1, 512, gid, stride);
    split_w(g_eWh1h, g_eWh1l, eWh1, 512, gid, stride);
    split_w(g_dWh0h, g_dWh0l, dWh0, 512, gid, stride);
    split_w(g_dWi1h, g_dWi1l, dWi1, 512, gid, stride);
    split_w(g_dWh1h, g_dWh1l, dWh1, 512, gid, stride);

    const int b = blockIdx.x;
    if (b < Bq) {
        float s = 0.0f;
        for (int i = tid; i < PRED * 8; i += blockDim.x) s += Xd[b * PRED * 8 + i];
        __shared__ float red[INTHR];
        red[tid] = s;
        __syncthreads();
        for (int off = INTHR / 2; off > 0; off >>= 1) {
            if (tid < off) red[tid] += red[tid + off];
            __syncthreads();
        }
        if (tid == 0) g_dec_in0[b] = red[0];
    }
}

// ---------------- persistent seq2seq kernel ----------------
__global__ __launch_bounds__(NTHR, 1) void seq2seq_kernel(
    const float* __restrict__ y, const int* __restrict__ tfm,
    const float* __restrict__ ebi0, const float* __restrict__ ebh0,
    const float* __restrict__ ebi1, const float* __restrict__ ebh1,
    const float* __restrict__ dWi0,
    const float* __restrict__ dbi0, const float* __restrict__ dbh0,
    const float* __restrict__ dbi1, const float* __restrict__ dbh1,
    const float* __restrict__ fcW, const float* __restrict__ fcB,
    float* __restrict__ d_out) {
    extern __shared__ __align__(128) char s_raw[];

    const int tileM = blockIdx.x >> 4;   // 0..7
    const int tileN = blockIdx.x & 15;   // 0..15
    const int bm0 = tileM * BM;
    const int hc0 = tileN * 32;
    const size_t woff512 = (size_t)tileN * 128 * 512;
    const size_t woff128 = (size_t)tileN * 128 * 128;

    float c0r[8], c1r[8];
#pragma unroll
    for (int qq = 0; qq < 8; ++qq) { c0r[qq] = 0.0f; c1r[qq] = 0.0f; }

    unsigned int phase = 0;
    int par = 0;
    float acc0[2][4][4], acc1[2][4][4];

#define ZERO_ACC(A) do { _Pragma("unroll") for (int _m = 0; _m < 2; ++_m) \
    _Pragma("unroll") for (int _j = 0; _j < 4; ++_j) \
    _Pragma("unroll") for (int _k = 0; _k < 4; ++_k) (A)[_m][_j][_k] = 0.0f; } while (0)

    // ---------------- encoder (wavefront: layer0(t=s) + layer1(t=s-1)) ----------
    for (int s = 0; s < T_ENC; ++s) {
        const __half* hr0 = g_h0[par];
        __half* hw0 = g_h0[par ^ 1];
        const __half* hr1 = g_h1[par];
        __half* hw1 = g_h1[par ^ 1];

        ZERO_ACC(acc0);
        if (s > 0) {
            ZERO_ACC(acc1);
            // one fused pipeline: [h0@eWh0 | x@eWi0] -> acc0 ; [h0@eWi1 | h1@eWh1] -> acc1
            gemm_pipe(acc0, acc1, s_raw,
                      hr0, Hd, g_eWh0h + woff512, g_eWh0l + woff512, 8,
                      g_X + (size_t)s * FEAT, (size_t)T_ENC * FEAT,
                      g_eWi0h + woff128, g_eWi0l + woff128, 2,
                      hr0, Hd, g_eWi1h + woff512, g_eWi1l + woff512, 8,
                      hr1, Hd, g_eWh1h + woff512, g_eWh1l + woff512, 8,
                      10, bm0);
            epilogue<0>(acc0, s_raw, c0r, ebi0, ebh0, hw0, bm0, hc0, tileN,
                        (const float*)0, (const float*)0, (const int*)0, (float*)0, s,
                        (const float*)0, (const float*)0);
            epilogue<0>(acc1, s_raw, c1r, ebi1, ebh1, hw1, bm0, hc0, tileN,
                        (const float*)0, (const float*)0, (const int*)0, (float*)0, s,
                        (const float*)0, (const float*)0);
        } else {
            gemm_pipe(acc0, acc0, s_raw,
                      hr0, Hd, g_eWh0h + woff512, g_eWh0l + woff512, 8,
                      g_X + (size_t)s * FEAT, (size_t)T_ENC * FEAT,
                      g_eWi0h + woff128, g_eWi0l + woff128, 2,
                      (const __half*)0, 0, (const __half*)0, (const __half*)0, 0,
                      (const __half*)0, 0, (const __half*)0, (const __half*)0, 0,
                      10, bm0);
            epilogue<0>(acc0, s_raw, c0r, ebi0, ebh0, hw0, bm0, hc0, tileN,
                        (const float*)0, (const float*)0, (const int*)0, (float*)0, s,
                        (const float*)0, (const float*)0);
        }
        grid_bar(&phase);
        par ^= 1;
    }

    // tail stage: layer1(t=T_ENC-1), plus copy final h0 across double buffer
    // FIXED vs R12: second K=512 segment goes in slot 2 (stride 512), slot 1 unused.
    {
        const __half* hr0 = g_h0[par];
        __half* hw0 = g_h0[par ^ 1];
        const __half* hr1 = g_h1[par];
        __half* hw1 = g_h1[par ^ 1];

        ZERO_ACC(acc0);
        gemm_pipe(acc0, acc0, s_raw,
                  hr0, Hd, g_eWi1h + woff512, g_eWi1l + woff512, 8,
                  (const __half*)0, 0, (const __half*)0, (const __half*)0, 0,
                  hr1, Hd, g_eWh1h + woff512, g_eWh1l + woff512, 8,
                  (const __half*)0, 0, (const __half*)0, (const __half*)0, 0,
                  16, bm0);
        epilogue<0>(acc0, s_raw, c1r, ebi1, ebh1, hw1, bm0, hc0, tileN,
                    (const float*)0, (const float*)0, (const int*)0, (float*)0, T_ENC,
                    (const float*)0, (const float*)0);

        for (int i = threadIdx.x; i < BM * 32; i += NTHR) {
            const int r = bm0 + (i >> 5), cc = hc0 + (i & 31);
            hw0[r * Hd + cc] = hr0[r * Hd + cc];
        }
        grid_bar(&phase);
        par ^= 1;
    }

    // ---------------- decoder ----------------
    for (int t = 0; t < PRED; ++t) {
        const __half* hr0 = g_h0[par];
        __half* hw0 = g_h0[par ^ 1];
        const __half* hr1 = g_h1[par];
        __half* hw1 = g_h1[par ^ 1];

        // stage A: gates0 = h0 @ dWh0^T  (+ din * dWi0 in epilogue)
        ZERO_ACC(acc0);
        gemm_pipe(acc0, acc0, s_raw,
                  hr0, Hd, g_dWh0h + woff512, g_dWh0l + woff512, 8,
                  (const __half*)0, 0, (const __half*)0, (const __half*)0, 0,
                  (const __half*)0, 0, (const __half*)0, (const __half*)0, 0,
                  (const __half*)0, 0, (const __half*)0, (const __half*)0, 0,
                  8, bm0);
        epilogue<1>(acc0, s_raw, c0r, dbi0, dbh0, hw0, bm0, hc0, tileN,
                    dWi0, y, tfm, d_out, t, (const float*)0, fcB);
        grid_bar(&phase);

        // stage B
        ZERO_ACC(acc0);
        gemm_pipe(acc0, acc0, s_raw,
                  hw0, Hd, g_dWi1h + woff512, g_dWi1l + woff512, 8,
                  (const __half*)0, 0, (const __half*)0, (const __half*)0, 0,
                  hr1, Hd, g_dWh1h + woff512, g_dWh1l + woff512, 8,
                  (const __half*)0, 0, (const __half*)0, (const __half*)0, 0,
                  16, bm0);
        epilogue<2>(acc0, s_raw, c1r, dbi1, dbh1, hw1, bm0, hc0, tileN,
                    (const float*)0, (const float*)0, (const int*)0, (float*)0, t,
                    fcW, (const float*)0);
        grid_bar(&phase);
        par ^= 1;
    }

    // ---------------- final output (t = PRED-1) ----------------
    if (tileN == 0 && threadIdx.x < BM) {
        const int b = bm0 + threadIdx.x;
        float out = fcB[0];
#pragma unroll
        for (int j = 0; j < 16; ++j) out += g_fc_part[j][b];
        d_out[b * PRED + (PRED - 1)] = out;
    }
}

// ---------------- harness entry ----------------
extern "C" void kernel_launch(void* const* d_in, const int* in_sizes, int n_in,
                              void* d_out, int out_size) {
    const float* Xe  = (const float*)d_in[0];
    const float* Xd  = (const float*)d_in[1];
    const float* y   = (const float*)d_in[2];
    const int*   tfm = (const int*)d_in[3];
    const float* eWi0 = (const float*)d_in[4];
    const float* eWh0 = (const float*)d_in[5];
    const float* ebi0 = (const float*)d_in[6];
    const float* ebh0 = (const float*)d_in[7];
    const float* eWi1 = (const float*)d_in[8];
    const float* eWh1 = (const float*)d_in[9];
    const float* ebi1 = (const float*)d_in[10];
    const float* ebh1 = (const float*)d_in[11];
    const float* dWi0 = (const float*)d_in[12];
    const float* dWh0 = (const float*)d_in[13];
    const float* dbi0 = (const float*)d_in[14];
    const float* dbh0 = (const float*)d_in[15];
    const float* dWi1 = (const float*)d_in[16];
    const float* dWh1 = (const float*)d_in[17];
    const float* dbi1 = (const float*)d_in[18];
    const float* dbh1 = (const float*)d_in[19];
    const float* fcW  = (const float*)d_in[20];
    const float* fcB  = (const float*)d_in[21];
    float* out = (float*)d_out;

    cudaFuncSetAttribute(seq2seq_kernel,
                         cudaFuncAttributeMaxDynamicSharedMemorySize, SMEM_BYTES);

    init_kernel<<<1024, INTHR>>>(Xd, Xe, eWi0, eWh0, eWi1, eWh1, dWh0, dWi1, dWh1);
    seq2seq_kernel<<<GRIDSZ, NTHR, SMEM_BYTES>>>(y, tfm,
                                                 ebi0, ebh0, ebi1, ebh1,
                                                 dWi0, dbi0, dbh0, dbi1, dbh1,
                                                 fcW, fcB, out);
}